// round 9
// baseline (speedup 1.0000x reference)
#include <cuda_runtime.h>
#include <cstdint>
#include <cstddef>

#define Gn   32
#define NN   1200
#define EE   19200
#define SUMH 1024

// conv dynamic smem: image tile [140 cols][92 rows] + 169 float4 weights
#define CONV_IMG_FLOATS (140 * 92)
#define CONV_SMEM_BYTES (CONV_IMG_FLOATS * 4 + 169 * 16)

// ---------------- static scratch (no cudaMalloc allowed) ----------------
__device__ float g_hcat[(size_t)Gn * NN * SUMH];   // concat(h1..h4), conv input
__device__ float g_A[(size_t)Gn * NN * 256];       // aggregated features per layer
__device__ int   g_rowptr[Gn * (NN + 1)];
__device__ int   g_esrc[Gn * EE];
__device__ float g_esc[Gn * EE];                   // per-edge s_out scale
__device__ float g_sin[Gn * NN];

// ---------------- CSR build + degree scales (one CTA per graph) ----------------
__global__ void build_csr_kernel(const int* __restrict__ src, const int* __restrict__ dst) {
    __shared__ int s_in[NN];
    __shared__ int s_out[NN];
    __shared__ int s_ptr[NN + 1];
    int g = blockIdx.x, t = threadIdx.x;
    for (int i = t; i < NN; i += blockDim.x) { s_in[i] = 0; s_out[i] = 0; }
    __syncthreads();
    const int* sg = src + g * EE;
    const int* dg = dst + g * EE;
    for (int e = t; e < EE; e += blockDim.x) {
        atomicAdd(&s_out[sg[e]], 1);
        atomicAdd(&s_in[dg[e]], 1);
    }
    __syncthreads();
    for (int i = t; i < NN; i += blockDim.x) {
        int id = s_in[i] < 1 ? 1 : s_in[i];
        g_sin[g * NN + i] = rsqrtf((float)id);
    }
    if (t == 0) {
        int run = 0;
        for (int i = 0; i < NN; i++) { s_ptr[i] = run; run += s_in[i]; }
        s_ptr[NN] = run;
    }
    __syncthreads();
    for (int i = t; i <= NN; i += blockDim.x) g_rowptr[g * (NN + 1) + i] = s_ptr[i];
    for (int i = t; i < NN; i += blockDim.x) s_in[i] = s_ptr[i];   // write cursors
    __syncthreads();
    for (int e = t; e < EE; e += blockDim.x) {
        int d = dg[e];
        int s = sg[e];
        int pos = atomicAdd(&s_in[d], 1);
        int od = s_out[s] < 1 ? 1 : s_out[s];
        g_esrc[g * EE + pos] = s;
        g_esc[g * EE + pos]  = rsqrtf((float)od);
    }
}

// ---------------- SpMM: A[v] = s_in[v] * sum_{e: dst=v} h[src_e] * s_out[src_e] ----------------
template <int D, bool FROM_HCAT>
__global__ __launch_bounds__(256) void spmm_kernel(const float* __restrict__ hext, int col_off) {
    constexpr int LPN = D / 4;          // threads per node
    constexpr int NPB = 256 / LPN;      // nodes per CTA
    int g = blockIdx.y;
    int lane = threadIdx.x & (LPN - 1);
    int ni   = threadIdx.x / LPN;
    int v = blockIdx.x * NPB + ni;

    const int* rp = g_rowptr + g * (NN + 1);
    int beg = rp[v], end = rp[v + 1];
    const int*   es  = g_esrc + g * EE;
    const float* esc = g_esc  + g * EE;

    float4 acc = make_float4(0.f, 0.f, 0.f, 0.f);
    const float* base;
    size_t rstride;
    if (FROM_HCAT) { base = g_hcat + (size_t)g * NN * SUMH + col_off + 4 * lane; rstride = SUMH; }
    else           { base = hext   + (size_t)g * NN * D    + 4 * lane;           rstride = D;    }

    #pragma unroll 4
    for (int e = beg; e < end; e++) {
        int s = es[e];
        float sc = esc[e];
        float4 hv = *(const float4*)(base + (size_t)s * rstride);
        acc.x += hv.x * sc; acc.y += hv.y * sc;
        acc.z += hv.z * sc; acc.w += hv.w * sc;
    }
    float si = g_sin[g * NN + v];
    acc.x *= si; acc.y *= si; acc.z *= si; acc.w *= si;
    *(float4*)(g_A + ((size_t)g * NN + v) * D + 4 * lane) = acc;
}

// ---------------- GEMM + bias + ReLU: h = relu(A(1200xK) @ W(Kx256) + b) -> g_hcat cols ----------------
template <int K>
__global__ __launch_bounds__(256) void gemm_kernel(const float* __restrict__ W,
                                                   const float* __restrict__ bias,
                                                   int col_off) {
    __shared__ float As[2][16][132];
    __shared__ float Bs[2][16][132];
    int g = blockIdx.z;
    int m0 = blockIdx.x * 128, n0 = blockIdx.y * 128;
    int tid = threadIdx.x;
    int tx = tid & 15, ty = tid >> 4;

    float acc[8][8];
    #pragma unroll
    for (int i = 0; i < 8; i++)
        #pragma unroll
        for (int j = 0; j < 8; j++) acc[i][j] = 0.f;

    int arow = tid >> 1;
    int acol = (tid & 1) * 8;
    int brow = tid >> 4;
    int bcol = (tid & 15) * 8;

    const float* Ag = g_A + (size_t)g * NN * K;
    bool a_ok = (m0 + arow) < NN;
    const float* aptr = Ag + (size_t)(m0 + arow) * K + acol;
    const float* bptr = W + (size_t)brow * 256 + n0 + bcol;

    {
        float4 a0, a1;
        if (a_ok) { a0 = *(const float4*)(aptr); a1 = *(const float4*)(aptr + 4); }
        else      { a0 = make_float4(0.f,0.f,0.f,0.f); a1 = a0; }
        float4 b0 = *(const float4*)(bptr);
        float4 b1 = *(const float4*)(bptr + 4);
        As[0][acol + 0][arow] = a0.x; As[0][acol + 1][arow] = a0.y;
        As[0][acol + 2][arow] = a0.z; As[0][acol + 3][arow] = a0.w;
        As[0][acol + 4][arow] = a1.x; As[0][acol + 5][arow] = a1.y;
        As[0][acol + 6][arow] = a1.z; As[0][acol + 7][arow] = a1.w;
        *(float4*)&Bs[0][brow][bcol]     = b0;
        *(float4*)&Bs[0][brow][bcol + 4] = b1;
    }
    __syncthreads();

    int buf = 0;
    for (int k0 = 0; k0 < K; k0 += 16) {
        int kn = k0 + 16;
        bool have_next = kn < K;
        float4 a0, a1, b0, b1;
        if (have_next) {
            if (a_ok) { a0 = *(const float4*)(aptr + kn); a1 = *(const float4*)(aptr + kn + 4); }
            else      { a0 = make_float4(0.f,0.f,0.f,0.f); a1 = a0; }
            b0 = *(const float4*)(bptr + (size_t)kn * 256);
            b1 = *(const float4*)(bptr + (size_t)kn * 256 + 4);
        }
        #pragma unroll
        for (int k = 0; k < 16; k++) {
            float4 alo = *(const float4*)&As[buf][k][4 * ty];
            float4 ahi = *(const float4*)&As[buf][k][64 + 4 * ty];
            float4 blo = *(const float4*)&Bs[buf][k][4 * tx];
            float4 bhi = *(const float4*)&Bs[buf][k][64 + 4 * tx];
            float af[8] = {alo.x, alo.y, alo.z, alo.w, ahi.x, ahi.y, ahi.z, ahi.w};
            float bf[8] = {blo.x, blo.y, blo.z, blo.w, bhi.x, bhi.y, bhi.z, bhi.w};
            #pragma unroll
            for (int i = 0; i < 8; i++)
                #pragma unroll
                for (int j = 0; j < 8; j++) acc[i][j] += af[i] * bf[j];
        }
        if (have_next) {
            int nb = buf ^ 1;
            As[nb][acol + 0][arow] = a0.x; As[nb][acol + 1][arow] = a0.y;
            As[nb][acol + 2][arow] = a0.z; As[nb][acol + 3][arow] = a0.w;
            As[nb][acol + 4][arow] = a1.x; As[nb][acol + 5][arow] = a1.y;
            As[nb][acol + 6][arow] = a1.z; As[nb][acol + 7][arow] = a1.w;
            *(float4*)&Bs[nb][brow][bcol]     = b0;
            *(float4*)&Bs[nb][brow][bcol + 4] = b1;
            __syncthreads();
            buf = nb;
        }
    }

    float4 bv[2];
    bv[0] = *(const float4*)&bias[n0 + 4 * tx];
    bv[1] = *(const float4*)&bias[n0 + 64 + 4 * tx];
    const float* bvp = (const float*)bv;
    #pragma unroll
    for (int ih = 0; ih < 2; ih++) {
        #pragma unroll
        for (int di = 0; di < 4; di++) {
            int m = m0 + 64 * ih + 4 * ty + di;
            if (m < NN) {
                float* orow = g_hcat + ((size_t)g * NN + m) * SUMH + col_off + n0;
                #pragma unroll
                for (int jh = 0; jh < 2; jh++) {
                    float4 v;
                    float* vp = (float*)&v;
                    #pragma unroll
                    for (int dj = 0; dj < 4; dj++) {
                        float x = acc[4 * ih + di][4 * jh + dj] + bvp[4 * jh + dj];
                        vp[dj] = x > 0.f ? x : 0.f;
                    }
                    *(float4*)&orow[64 * jh + 4 * tx] = v;
                }
            }
        }
    }
}

// ---------------- fused 13x13 conv (1->3 ch) + max-pool ----------------
// CTA = (col tile 128, PAIR of pool blocks = 80 rows, graph). 512 thr =
// 128 cols x 4 row-groups of T=20 output rows. Groups {0,1} -> pool block 2p,
// {2,3} -> 2p+1. DYNAMIC smem: image tile column-major [140][92] + float4
// weight table. 92-float column stride: 16B-aligned, conflict-free LDS.128;
// group bases {0,20,40,60} are 16B-aligned.
__global__ __launch_bounds__(512) void conv_pool_kernel(const float* __restrict__ cw,
                                                        const float* __restrict__ cb,
                                                        float* __restrict__ out,
                                                        int ct_base) {
    extern __shared__ float s_dyn[];
    float  (*s_img)[92] = reinterpret_cast<float (*)[92]>(s_dyn);   // [col][row]
    float4* s_w4 = reinterpret_cast<float4*>(s_dyn + CONV_IMG_FLOATS); // 51520B offset, 16B-aligned

    int ct = blockIdx.x + ct_base, p = blockIdx.y, g = blockIdx.z;
    int tid = threadIdx.x;
    for (int i = tid; i < 169; i += 512)
        s_w4[i] = make_float4(cw[i], cw[169 + i], cw[338 + i], 0.f);

    int base_r = p * 80 - 6, base_c = ct * 128 - 6;
    const float* hg = g_hcat + (size_t)g * NN * SUMH;
    for (int idx = tid; idx < 92 * 140; idx += 512) {
        int r = idx / 140, c = idx - r * 140;
        int gr = base_r + r, gc = base_c + c;
        float v = 0.f;
        if (gr >= 0 && gr < NN && gc >= 0 && gc < SUMH)
            v = hg[(size_t)gr * SUMH + gc];
        s_img[c][r] = v;
    }
    __syncthreads();

    int tx = tid & 127, ty = tid >> 7;   // 4 row-groups of 20 output rows
    int rbase = 20 * ty;                 // {0,20,40,60}
    float mx0 = -1e30f, mx1 = -1e30f, mx2 = -1e30f;

    {
        float acc0[20], acc1[20], acc2[20];
        #pragma unroll
        for (int t = 0; t < 20; t++) { acc0[t] = 0.f; acc1[t] = 0.f; acc2[t] = 0.f; }
        #pragma unroll 1
        for (int kc = 0; kc < 13; kc++) {
            float v[32];
            const float4* vcol = (const float4*)&s_img[tx + kc][rbase];
            #pragma unroll
            for (int q = 0; q < 8; q++) {
                float4 t4 = vcol[q];
                v[4 * q + 0] = t4.x; v[4 * q + 1] = t4.y;
                v[4 * q + 2] = t4.z; v[4 * q + 3] = t4.w;
            }
            #pragma unroll
            for (int kr = 0; kr < 13; kr++) {
                float4 w = s_w4[kr * 13 + kc];
                #pragma unroll
                for (int t = 0; t < 20; t++) {
                    float x = v[kr + t];
                    acc0[t] += x * w.x;
                    acc1[t] += x * w.y;
                    acc2[t] += x * w.z;
                }
            }
        }
        #pragma unroll
        for (int t = 0; t < 20; t++) {
            mx0 = fmaxf(mx0, acc0[t]);
            mx1 = fmaxf(mx1, acc1[t]);
            mx2 = fmaxf(mx2, acc2[t]);
        }
    }

    __syncthreads();                 // done reading s_img; reuse for reduction
    float* red = s_dyn;              // 2 halves x 3 ch x 128 cols = 768 floats
    if (ty & 1) {                    // groups 1,3 publish partials
        int half = ty >> 1;
        red[(half * 3 + 0) * 128 + tx] = mx0;
        red[(half * 3 + 1) * 128 + tx] = mx1;
        red[(half * 3 + 2) * 128 + tx] = mx2;
    }
    __syncthreads();
    if (!(ty & 1)) {                 // groups 0,2 combine + store
        int half = ty >> 1;
        mx0 = fmaxf(mx0, red[(half * 3 + 0) * 128 + tx]);
        mx1 = fmaxf(mx1, red[(half * 3 + 1) * 128 + tx]);
        mx2 = fmaxf(mx2, red[(half * 3 + 2) * 128 + tx]);
        int pb = p * 2 + half;
        int c = ct * 128 + tx;
        out[((size_t)(g * 3 + 0) * 30 + pb) * SUMH + c] = mx0 + cb[0];
        out[((size_t)(g * 3 + 1) * 30 + pb) * SUMH + c] = mx1 + cb[1];
        out[((size_t)(g * 3 + 2) * 30 + pb) * SUMH + c] = mx2 + cb[2];
    }
}

// ---------------- side stream + events + smem opt-in (static init; no tracked device allocs) ----------------
struct PipeRes {
    cudaStream_t sc = nullptr;
    cudaEvent_t e1 = nullptr, e2 = nullptr, e3 = nullptr, e4 = nullptr, ej = nullptr;
    PipeRes() {
        cudaStreamCreateWithFlags(&sc, cudaStreamNonBlocking);
        cudaEventCreateWithFlags(&e1, cudaEventDisableTiming);
        cudaEventCreateWithFlags(&e2, cudaEventDisableTiming);
        cudaEventCreateWithFlags(&e3, cudaEventDisableTiming);
        cudaEventCreateWithFlags(&e4, cudaEventDisableTiming);
        cudaEventCreateWithFlags(&ej, cudaEventDisableTiming);
        cudaFuncSetAttribute(conv_pool_kernel,
                             cudaFuncAttributeMaxDynamicSharedMemorySize, CONV_SMEM_BYTES);
    }
};
static PipeRes g_pipe;

// ---------------- driver ----------------
extern "C" void kernel_launch(void* const* d_in, const int* in_sizes, int n_in,
                              void* d_out, int out_size) {
    const float* feat = (const float*)d_in[0];
    const int*   src  = (const int*)d_in[1];
    const int*   dst  = (const int*)d_in[2];
    const float* W1 = (const float*)d_in[3];  const float* b1 = (const float*)d_in[4];
    const float* W2 = (const float*)d_in[5];  const float* b2 = (const float*)d_in[6];
    const float* W3 = (const float*)d_in[7];  const float* b3 = (const float*)d_in[8];
    const float* W4 = (const float*)d_in[9];  const float* b4 = (const float*)d_in[10];
    const float* cw = (const float*)d_in[11]; const float* cb = (const float*)d_in[12];
    float* out = (float*)d_out;

    cudaStream_t s0 = (cudaStream_t)0;
    cudaStream_t sc = g_pipe.sc;

    build_csr_kernel<<<Gn, 256, 0, s0>>>(src, dst);

    // layer 1
    spmm_kernel<128, false><<<dim3(NN / 8, Gn), 256, 0, s0>>>(feat, 0);
    gemm_kernel<128><<<dim3(10, 2, Gn), 256, 0, s0>>>(W1, b1, 0);
    cudaEventRecord(g_pipe.e1, s0);
    // tile 0 reads cols <= 133 -> h1 only
    cudaStreamWaitEvent(sc, g_pipe.e1, 0);
    conv_pool_kernel<<<dim3(1, 15, Gn), 512, CONV_SMEM_BYTES, sc>>>(cw, cb, out, 0);

    // layer 2
    spmm_kernel<256, true><<<dim3(NN / 4, Gn), 256, 0, s0>>>(nullptr, 0);
    gemm_kernel<256><<<dim3(10, 2, Gn), 256, 0, s0>>>(W2, b2, 256);
    cudaEventRecord(g_pipe.e2, s0);
    // tiles 1,2 read cols <= 389 -> h1,h2
    cudaStreamWaitEvent(sc, g_pipe.e2, 0);
    conv_pool_kernel<<<dim3(2, 15, Gn), 512, CONV_SMEM_BYTES, sc>>>(cw, cb, out, 1);

    // layer 3
    spmm_kernel<256, true><<<dim3(NN / 4, Gn), 256, 0, s0>>>(nullptr, 256);
    gemm_kernel<256><<<dim3(10, 2, Gn), 256, 0, s0>>>(W3, b3, 512);
    cudaEventRecord(g_pipe.e3, s0);
    // tiles 3,4 read cols <= 645 -> h1..h3
    cudaStreamWaitEvent(sc, g_pipe.e3, 0);
    conv_pool_kernel<<<dim3(2, 15, Gn), 512, CONV_SMEM_BYTES, sc>>>(cw, cb, out, 3);

    // layer 4
    spmm_kernel<256, true><<<dim3(NN / 4, Gn), 256, 0, s0>>>(nullptr, 512);
    gemm_kernel<256><<<dim3(10, 2, Gn), 256, 0, s0>>>(W4, b4, 768);
    cudaEventRecord(g_pipe.e4, s0);
    // tiles 5..7 need h4
    cudaStreamWaitEvent(sc, g_pipe.e4, 0);
    conv_pool_kernel<<<dim3(3, 15, Gn), 512, CONV_SMEM_BYTES, sc>>>(cw, cb, out, 5);

    // join the fork back into the capture stream
    cudaEventRecord(g_pipe.ej, sc);
    cudaStreamWaitEvent(s0, g_pipe.ej, 0);
}

// round 10
// speedup vs baseline: 1.0944x; 1.0944x over previous
#include <cuda_runtime.h>
#include <cstdint>
#include <cstddef>

#define Gn   32
#define NN   1200
#define EE   19200
#define SUMH 1024

// ---------------- static scratch (no cudaMalloc allowed) ----------------
__device__ float g_hcat[(size_t)Gn * NN * SUMH];   // concat(h1..h4), conv input
__device__ float g_A[(size_t)Gn * NN * 256];       // aggregated features per layer
__device__ int   g_rowptr[Gn * (NN + 1)];
__device__ int   g_esrc[Gn * EE];
__device__ float g_esc[Gn * EE];                   // per-edge s_out scale
__device__ float g_sin[Gn * NN];

// ---------------- CSR build + degree scales (one CTA per graph) ----------------
__global__ void build_csr_kernel(const int* __restrict__ src, const int* __restrict__ dst) {
    __shared__ int s_in[NN];
    __shared__ int s_out[NN];
    __shared__ int s_ptr[NN + 1];
    int g = blockIdx.x, t = threadIdx.x;
    for (int i = t; i < NN; i += blockDim.x) { s_in[i] = 0; s_out[i] = 0; }
    __syncthreads();
    const int* sg = src + g * EE;
    const int* dg = dst + g * EE;
    for (int e = t; e < EE; e += blockDim.x) {
        atomicAdd(&s_out[sg[e]], 1);
        atomicAdd(&s_in[dg[e]], 1);
    }
    __syncthreads();
    for (int i = t; i < NN; i += blockDim.x) {
        int id = s_in[i] < 1 ? 1 : s_in[i];
        g_sin[g * NN + i] = rsqrtf((float)id);
    }
    if (t == 0) {
        int run = 0;
        for (int i = 0; i < NN; i++) { s_ptr[i] = run; run += s_in[i]; }
        s_ptr[NN] = run;
    }
    __syncthreads();
    for (int i = t; i <= NN; i += blockDim.x) g_rowptr[g * (NN + 1) + i] = s_ptr[i];
    for (int i = t; i < NN; i += blockDim.x) s_in[i] = s_ptr[i];   // write cursors
    __syncthreads();
    for (int e = t; e < EE; e += blockDim.x) {
        int d = dg[e];
        int s = sg[e];
        int pos = atomicAdd(&s_in[d], 1);
        int od = s_out[s] < 1 ? 1 : s_out[s];
        g_esrc[g * EE + pos] = s;
        g_esc[g * EE + pos]  = rsqrtf((float)od);
    }
}

// ---------------- SpMM: A[v] = s_in[v] * sum_{e: dst=v} h[src_e] * s_out[src_e] ----------------
template <int D, bool FROM_HCAT>
__global__ __launch_bounds__(256) void spmm_kernel(const float* __restrict__ hext, int col_off) {
    constexpr int LPN = D / 4;          // threads per node
    constexpr int NPB = 256 / LPN;      // nodes per CTA
    int g = blockIdx.y;
    int lane = threadIdx.x & (LPN - 1);
    int ni   = threadIdx.x / LPN;
    int v = blockIdx.x * NPB + ni;

    const int* rp = g_rowptr + g * (NN + 1);
    int beg = rp[v], end = rp[v + 1];
    const int*   es  = g_esrc + g * EE;
    const float* esc = g_esc  + g * EE;

    float4 acc = make_float4(0.f, 0.f, 0.f, 0.f);
    const float* base;
    size_t rstride;
    if (FROM_HCAT) { base = g_hcat + (size_t)g * NN * SUMH + col_off + 4 * lane; rstride = SUMH; }
    else           { base = hext   + (size_t)g * NN * D    + 4 * lane;           rstride = D;    }

    #pragma unroll 4
    for (int e = beg; e < end; e++) {
        int s = es[e];
        float sc = esc[e];
        float4 hv = *(const float4*)(base + (size_t)s * rstride);
        acc.x += hv.x * sc; acc.y += hv.y * sc;
        acc.z += hv.z * sc; acc.w += hv.w * sc;
    }
    float si = g_sin[g * NN + v];
    acc.x *= si; acc.y *= si; acc.z *= si; acc.w *= si;
    *(float4*)(g_A + ((size_t)g * NN + v) * D + 4 * lane) = acc;
}

// ---------------- GEMM + bias + ReLU: h = relu(A(1200xK) @ W(Kx256) + b) -> g_hcat cols ----------------
// 64x128 CTA tile, BK=16, 256 threads, 4x8 microtile (rows 4ty+di, cols 4tx+dj + 64*jh),
// double-buffered smem, LDS.128 fragment loads. 3 CTAs/SM kills the wave-quantization tail
// (grid 19x2x32 = 1216 CTAs over 444 slots = 91% util vs 72% for the 128x128 tiling).
template <int K>
__global__ __launch_bounds__(256, 3) void gemm_kernel(const float* __restrict__ W,
                                                      const float* __restrict__ bias,
                                                      int col_off) {
    __shared__ float As[2][16][68];
    __shared__ float Bs[2][16][132];
    int g = blockIdx.z;
    int m0 = blockIdx.x * 64, n0 = blockIdx.y * 128;
    int tid = threadIdx.x;
    int tx = tid & 15, ty = tid >> 4;

    float acc[4][8];
    #pragma unroll
    for (int i = 0; i < 4; i++)
        #pragma unroll
        for (int j = 0; j < 8; j++) acc[i][j] = 0.f;

    int arow = tid >> 2;          // 0..63
    int acol = (tid & 3) * 4;     // 0,4,8,12
    int brow = tid >> 4;          // 0..15
    int bcol = (tid & 15) * 8;    // 0..120

    const float* Ag = g_A + (size_t)g * NN * K;
    bool a_ok = (m0 + arow) < NN;
    const float* aptr = Ag + (size_t)(m0 + arow) * K + acol;
    const float* bptr = W + (size_t)brow * 256 + n0 + bcol;

    // preload tile 0 into buffer 0
    {
        float4 a0;
        if (a_ok) a0 = *(const float4*)(aptr);
        else      a0 = make_float4(0.f, 0.f, 0.f, 0.f);
        float4 b0 = *(const float4*)(bptr);
        float4 b1 = *(const float4*)(bptr + 4);
        As[0][acol + 0][arow] = a0.x; As[0][acol + 1][arow] = a0.y;
        As[0][acol + 2][arow] = a0.z; As[0][acol + 3][arow] = a0.w;
        *(float4*)&Bs[0][brow][bcol]     = b0;
        *(float4*)&Bs[0][brow][bcol + 4] = b1;
    }
    __syncthreads();

    int buf = 0;
    for (int k0 = 0; k0 < K; k0 += 16) {
        int kn = k0 + 16;
        bool have_next = kn < K;
        float4 a0, b0, b1;
        if (have_next) {
            if (a_ok) a0 = *(const float4*)(aptr + kn);
            else      a0 = make_float4(0.f, 0.f, 0.f, 0.f);
            b0 = *(const float4*)(bptr + (size_t)kn * 256);
            b1 = *(const float4*)(bptr + (size_t)kn * 256 + 4);
        }
        #pragma unroll
        for (int k = 0; k < 16; k++) {
            float4 a4  = *(const float4*)&As[buf][k][4 * ty];
            float4 blo = *(const float4*)&Bs[buf][k][4 * tx];
            float4 bhi = *(const float4*)&Bs[buf][k][64 + 4 * tx];
            float af[4] = {a4.x, a4.y, a4.z, a4.w};
            float bf[8] = {blo.x, blo.y, blo.z, blo.w, bhi.x, bhi.y, bhi.z, bhi.w};
            #pragma unroll
            for (int i = 0; i < 4; i++)
                #pragma unroll
                for (int j = 0; j < 8; j++) acc[i][j] += af[i] * bf[j];
        }
        if (have_next) {
            int nb = buf ^ 1;
            As[nb][acol + 0][arow] = a0.x; As[nb][acol + 1][arow] = a0.y;
            As[nb][acol + 2][arow] = a0.z; As[nb][acol + 3][arow] = a0.w;
            *(float4*)&Bs[nb][brow][bcol]     = b0;
            *(float4*)&Bs[nb][brow][bcol + 4] = b1;
            __syncthreads();
            buf = nb;
        }
    }

    // epilogue: bias + relu, float4 stores
    float4 bv[2];
    bv[0] = *(const float4*)&bias[n0 + 4 * tx];
    bv[1] = *(const float4*)&bias[n0 + 64 + 4 * tx];
    const float* bvp = (const float*)bv;
    #pragma unroll
    for (int di = 0; di < 4; di++) {
        int m = m0 + 4 * ty + di;
        if (m < NN) {
            float* orow = g_hcat + ((size_t)g * NN + m) * SUMH + col_off + n0;
            #pragma unroll
            for (int jh = 0; jh < 2; jh++) {
                float4 v;
                float* vp = (float*)&v;
                #pragma unroll
                for (int dj = 0; dj < 4; dj++) {
                    float x = acc[di][4 * jh + dj] + bvp[4 * jh + dj];
                    vp[dj] = x > 0.f ? x : 0.f;
                }
                *(float4*)&orow[64 * jh + 4 * tx] = v;
            }
        }
    }
}

// ---------------- fused 13x13 conv (1->3 ch) + max-pool over 40-row blocks ----------------
// EXACT R6 design (proven fastest): CTA = (col tile 128 [blockIdx.x + ct_base],
// pool block 40 rows, graph). 256 thr = 128 cols x 2 halves (T=20 rows each).
// Image tile column-major [140 cols][52 rows]; channel weights packed as float4.
__global__ __launch_bounds__(256) void conv_pool_kernel(const float* __restrict__ cw,
                                                        const float* __restrict__ cb,
                                                        float* __restrict__ out,
                                                        int ct_base) {
    __shared__ float  s_img[140][52];    // [col][row]
    __shared__ float4 s_w4[169];         // {w_ch0, w_ch1, w_ch2, 0} per (kr*13+kc)
    int ct = blockIdx.x + ct_base, p = blockIdx.y, g = blockIdx.z;
    int tid = threadIdx.x;
    for (int i = tid; i < 169; i += 256)
        s_w4[i] = make_float4(cw[i], cw[169 + i], cw[338 + i], 0.f);

    int base_r = p * 40 - 6, base_c = ct * 128 - 6;
    const float* hg = g_hcat + (size_t)g * NN * SUMH;
    for (int idx = tid; idx < 52 * 140; idx += 256) {
        int r = idx / 140, c = idx - r * 140;
        int gr = base_r + r, gc = base_c + c;
        float v = 0.f;
        if (gr >= 0 && gr < NN && gc >= 0 && gc < SUMH)
            v = hg[(size_t)gr * SUMH + gc];
        s_img[c][r] = v;
    }
    __syncthreads();

    int tx = tid & 127, ty = tid >> 7;
    int rbase = ty * 20;
    float mx0 = -1e30f, mx1 = -1e30f, mx2 = -1e30f;

    {
        float acc0[20], acc1[20], acc2[20];
        #pragma unroll
        for (int t = 0; t < 20; t++) { acc0[t] = 0.f; acc1[t] = 0.f; acc2[t] = 0.f; }
        #pragma unroll 1
        for (int kc = 0; kc < 13; kc++) {
            float v[32];
            const float4* vcol = (const float4*)&s_img[tx + kc][rbase];
            #pragma unroll
            for (int q = 0; q < 8; q++) {
                float4 t4 = vcol[q];
                v[4 * q + 0] = t4.x; v[4 * q + 1] = t4.y;
                v[4 * q + 2] = t4.z; v[4 * q + 3] = t4.w;
            }
            #pragma unroll
            for (int kr = 0; kr < 13; kr++) {
                float4 w = s_w4[kr * 13 + kc];
                #pragma unroll
                for (int t = 0; t < 20; t++) {
                    float x = v[kr + t];
                    acc0[t] += x * w.x;
                    acc1[t] += x * w.y;
                    acc2[t] += x * w.z;
                }
            }
        }
        #pragma unroll
        for (int t = 0; t < 20; t++) {
            mx0 = fmaxf(mx0, acc0[t]);
            mx1 = fmaxf(mx1, acc1[t]);
            mx2 = fmaxf(mx2, acc2[t]);
        }
    }

    __syncthreads();                 // done reading s_img; reuse for reduction
    float* red = &s_img[0][0];
    if (ty == 1) { red[tx] = mx0; red[128 + tx] = mx1; red[256 + tx] = mx2; }
    __syncthreads();
    if (ty == 0) {
        mx0 = fmaxf(mx0, red[tx]);
        mx1 = fmaxf(mx1, red[128 + tx]);
        mx2 = fmaxf(mx2, red[256 + tx]);
        int c = ct * 128 + tx;
        out[((size_t)(g * 3 + 0) * 30 + p) * SUMH + c] = mx0 + cb[0];
        out[((size_t)(g * 3 + 1) * 30 + p) * SUMH + c] = mx1 + cb[1];
        out[((size_t)(g * 3 + 2) * 30 + p) * SUMH + c] = mx2 + cb[2];
    }
}

// ---------------- side stream + events (static init; no tracked device allocs) ----------------
struct PipeRes {
    cudaStream_t sc = nullptr;
    cudaEvent_t e1 = nullptr, e2 = nullptr, e3 = nullptr, e4 = nullptr, ej = nullptr;
    PipeRes() {
        cudaStreamCreateWithFlags(&sc, cudaStreamNonBlocking);
        cudaEventCreateWithFlags(&e1, cudaEventDisableTiming);
        cudaEventCreateWithFlags(&e2, cudaEventDisableTiming);
        cudaEventCreateWithFlags(&e3, cudaEventDisableTiming);
        cudaEventCreateWithFlags(&e4, cudaEventDisableTiming);
        cudaEventCreateWithFlags(&ej, cudaEventDisableTiming);
    }
};
static PipeRes g_pipe;

// ---------------- driver ----------------
extern "C" void kernel_launch(void* const* d_in, const int* in_sizes, int n_in,
                              void* d_out, int out_size) {
    const float* feat = (const float*)d_in[0];
    const int*   src  = (const int*)d_in[1];
    const int*   dst  = (const int*)d_in[2];
    const float* W1 = (const float*)d_in[3];  const float* b1 = (const float*)d_in[4];
    const float* W2 = (const float*)d_in[5];  const float* b2 = (const float*)d_in[6];
    const float* W3 = (const float*)d_in[7];  const float* b3 = (const float*)d_in[8];
    const float* W4 = (const float*)d_in[9];  const float* b4 = (const float*)d_in[10];
    const float* cw = (const float*)d_in[11]; const float* cb = (const float*)d_in[12];
    float* out = (float*)d_out;

    cudaStream_t s0 = (cudaStream_t)0;
    cudaStream_t sc = g_pipe.sc;

    build_csr_kernel<<<Gn, 256, 0, s0>>>(src, dst);

    // layer 1
    spmm_kernel<128, false><<<dim3(NN / 8, Gn), 256, 0, s0>>>(feat, 0);
    gemm_kernel<128><<<dim3(19, 2, Gn), 256, 0, s0>>>(W1, b1, 0);
    cudaEventRecord(g_pipe.e1, s0);
    // tile 0 reads cols <= 133 -> h1 only
    cudaStreamWaitEvent(sc, g_pipe.e1, 0);
    conv_pool_kernel<<<dim3(1, 30, Gn), 256, 0, sc>>>(cw, cb, out, 0);

    // layer 2
    spmm_kernel<256, true><<<dim3(NN / 4, Gn), 256, 0, s0>>>(nullptr, 0);
    gemm_kernel<256><<<dim3(19, 2, Gn), 256, 0, s0>>>(W2, b2, 256);
    cudaEventRecord(g_pipe.e2, s0);
    // tiles 1,2 read cols <= 389 -> h1,h2
    cudaStreamWaitEvent(sc, g_pipe.e2, 0);
    conv_pool_kernel<<<dim3(2, 30, Gn), 256, 0, sc>>>(cw, cb, out, 1);

    // layer 3
    spmm_kernel<256, true><<<dim3(NN / 4, Gn), 256, 0, s0>>>(nullptr, 256);
    gemm_kernel<256><<<dim3(19, 2, Gn), 256, 0, s0>>>(W3, b3, 512);
    cudaEventRecord(g_pipe.e3, s0);
    // tiles 3,4 read cols <= 645 -> h1..h3
    cudaStreamWaitEvent(sc, g_pipe.e3, 0);
    conv_pool_kernel<<<dim3(2, 30, Gn), 256, 0, sc>>>(cw, cb, out, 3);

    // layer 4
    spmm_kernel<256, true><<<dim3(NN / 4, Gn), 256, 0, s0>>>(nullptr, 512);
    gemm_kernel<256><<<dim3(19, 2, Gn), 256, 0, s0>>>(W4, b4, 768);
    cudaEventRecord(g_pipe.e4, s0);
    // tiles 5..7 need h4
    cudaStreamWaitEvent(sc, g_pipe.e4, 0);
    conv_pool_kernel<<<dim3(3, 30, Gn), 256, 0, sc>>>(cw, cb, out, 5);

    // join the fork back into the capture stream
    cudaEventRecord(g_pipe.ej, sc);
    cudaStreamWaitEvent(s0, g_pipe.ej, 0);
}

// round 11
// speedup vs baseline: 1.1299x; 1.0325x over previous
#include <cuda_runtime.h>
#include <cstdint>
#include <cstddef>

#define Gn   32
#define NN   1200
#define EE   19200
#define SUMH 1024

// ---------------- static scratch (no cudaMalloc allowed) ----------------
__device__ float g_hcat[(size_t)Gn * NN * SUMH];   // concat(h1..h4), conv input
__device__ float g_A[(size_t)Gn * NN * 256];       // aggregated features per layer
__device__ int   g_rowptr[Gn * (NN + 1)];
__device__ int   g_esrc[Gn * EE];
__device__ float g_esc[Gn * EE];                   // per-edge s_out scale
__device__ float g_sin[Gn * NN];

// ---------------- CSR build + degree scales (one CTA per graph) ----------------
__global__ void build_csr_kernel(const int* __restrict__ src, const int* __restrict__ dst) {
    __shared__ int s_in[NN];
    __shared__ int s_out[NN];
    __shared__ int s_ptr[NN + 1];
    int g = blockIdx.x, t = threadIdx.x;
    for (int i = t; i < NN; i += blockDim.x) { s_in[i] = 0; s_out[i] = 0; }
    __syncthreads();
    const int* sg = src + g * EE;
    const int* dg = dst + g * EE;
    for (int e = t; e < EE; e += blockDim.x) {
        atomicAdd(&s_out[sg[e]], 1);
        atomicAdd(&s_in[dg[e]], 1);
    }
    __syncthreads();
    for (int i = t; i < NN; i += blockDim.x) {
        int id = s_in[i] < 1 ? 1 : s_in[i];
        g_sin[g * NN + i] = rsqrtf((float)id);
    }
    if (t == 0) {
        int run = 0;
        for (int i = 0; i < NN; i++) { s_ptr[i] = run; run += s_in[i]; }
        s_ptr[NN] = run;
    }
    __syncthreads();
    for (int i = t; i <= NN; i += blockDim.x) g_rowptr[g * (NN + 1) + i] = s_ptr[i];
    for (int i = t; i < NN; i += blockDim.x) s_in[i] = s_ptr[i];   // write cursors
    __syncthreads();
    for (int e = t; e < EE; e += blockDim.x) {
        int d = dg[e];
        int s = sg[e];
        int pos = atomicAdd(&s_in[d], 1);
        int od = s_out[s] < 1 ? 1 : s_out[s];
        g_esrc[g * EE + pos] = s;
        g_esc[g * EE + pos]  = rsqrtf((float)od);
    }
}

// ---------------- SpMM: A[v] = s_in[v] * sum_{e: dst=v} h[src_e] * s_out[src_e] ----------------
template <int D, bool FROM_HCAT>
__global__ __launch_bounds__(256) void spmm_kernel(const float* __restrict__ hext, int col_off) {
    constexpr int LPN = D / 4;          // threads per node
    constexpr int NPB = 256 / LPN;      // nodes per CTA
    int g = blockIdx.y;
    int lane = threadIdx.x & (LPN - 1);
    int ni   = threadIdx.x / LPN;
    int v = blockIdx.x * NPB + ni;

    const int* rp = g_rowptr + g * (NN + 1);
    int beg = rp[v], end = rp[v + 1];
    const int*   es  = g_esrc + g * EE;
    const float* esc = g_esc  + g * EE;

    float4 acc = make_float4(0.f, 0.f, 0.f, 0.f);
    const float* base;
    size_t rstride;
    if (FROM_HCAT) { base = g_hcat + (size_t)g * NN * SUMH + col_off + 4 * lane; rstride = SUMH; }
    else           { base = hext   + (size_t)g * NN * D    + 4 * lane;           rstride = D;    }

    #pragma unroll 4
    for (int e = beg; e < end; e++) {
        int s = es[e];
        float sc = esc[e];
        float4 hv = *(const float4*)(base + (size_t)s * rstride);
        acc.x += hv.x * sc; acc.y += hv.y * sc;
        acc.z += hv.z * sc; acc.w += hv.w * sc;
    }
    float si = g_sin[g * NN + v];
    acc.x *= si; acc.y *= si; acc.z *= si; acc.w *= si;
    *(float4*)(g_A + ((size_t)g * NN + v) * D + 4 * lane) = acc;
}

// ---------------- GEMM + bias + ReLU: h = relu(A(1200xK) @ W(Kx256) + b) -> g_hcat cols ----------------
// 64x128 CTA tile, BK=16, 256 threads, 4x8 microtile, double-buffered smem, 3 CTAs/SM.
template <int K>
__global__ __launch_bounds__(256, 3) void gemm_kernel(const float* __restrict__ W,
                                                      const float* __restrict__ bias,
                                                      int col_off) {
    __shared__ float As[2][16][68];
    __shared__ float Bs[2][16][132];
    int g = blockIdx.z;
    int m0 = blockIdx.x * 64, n0 = blockIdx.y * 128;
    int tid = threadIdx.x;
    int tx = tid & 15, ty = tid >> 4;

    float acc[4][8];
    #pragma unroll
    for (int i = 0; i < 4; i++)
        #pragma unroll
        for (int j = 0; j < 8; j++) acc[i][j] = 0.f;

    int arow = tid >> 2;          // 0..63
    int acol = (tid & 3) * 4;     // 0,4,8,12
    int brow = tid >> 4;          // 0..15
    int bcol = (tid & 15) * 8;    // 0..120

    const float* Ag = g_A + (size_t)g * NN * K;
    bool a_ok = (m0 + arow) < NN;
    const float* aptr = Ag + (size_t)(m0 + arow) * K + acol;
    const float* bptr = W + (size_t)brow * 256 + n0 + bcol;

    {
        float4 a0;
        if (a_ok) a0 = *(const float4*)(aptr);
        else      a0 = make_float4(0.f, 0.f, 0.f, 0.f);
        float4 b0 = *(const float4*)(bptr);
        float4 b1 = *(const float4*)(bptr + 4);
        As[0][acol + 0][arow] = a0.x; As[0][acol + 1][arow] = a0.y;
        As[0][acol + 2][arow] = a0.z; As[0][acol + 3][arow] = a0.w;
        *(float4*)&Bs[0][brow][bcol]     = b0;
        *(float4*)&Bs[0][brow][bcol + 4] = b1;
    }
    __syncthreads();

    int buf = 0;
    for (int k0 = 0; k0 < K; k0 += 16) {
        int kn = k0 + 16;
        bool have_next = kn < K;
        float4 a0, b0, b1;
        if (have_next) {
            if (a_ok) a0 = *(const float4*)(aptr + kn);
            else      a0 = make_float4(0.f, 0.f, 0.f, 0.f);
            b0 = *(const float4*)(bptr + (size_t)kn * 256);
            b1 = *(const float4*)(bptr + (size_t)kn * 256 + 4);
        }
        #pragma unroll
        for (int k = 0; k < 16; k++) {
            float4 a4  = *(const float4*)&As[buf][k][4 * ty];
            float4 blo = *(const float4*)&Bs[buf][k][4 * tx];
            float4 bhi = *(const float4*)&Bs[buf][k][64 + 4 * tx];
            float af[4] = {a4.x, a4.y, a4.z, a4.w};
            float bf[8] = {blo.x, blo.y, blo.z, blo.w, bhi.x, bhi.y, bhi.z, bhi.w};
            #pragma unroll
            for (int i = 0; i < 4; i++)
                #pragma unroll
                for (int j = 0; j < 8; j++) acc[i][j] += af[i] * bf[j];
        }
        if (have_next) {
            int nb = buf ^ 1;
            As[nb][acol + 0][arow] = a0.x; As[nb][acol + 1][arow] = a0.y;
            As[nb][acol + 2][arow] = a0.z; As[nb][acol + 3][arow] = a0.w;
            *(float4*)&Bs[nb][brow][bcol]     = b0;
            *(float4*)&Bs[nb][brow][bcol + 4] = b1;
            __syncthreads();
            buf = nb;
        }
    }

    float4 bv[2];
    bv[0] = *(const float4*)&bias[n0 + 4 * tx];
    bv[1] = *(const float4*)&bias[n0 + 64 + 4 * tx];
    const float* bvp = (const float*)bv;
    #pragma unroll
    for (int di = 0; di < 4; di++) {
        int m = m0 + 4 * ty + di;
        if (m < NN) {
            float* orow = g_hcat + ((size_t)g * NN + m) * SUMH + col_off + n0;
            #pragma unroll
            for (int jh = 0; jh < 2; jh++) {
                float4 v;
                float* vp = (float*)&v;
                #pragma unroll
                for (int dj = 0; dj < 4; dj++) {
                    float x = acc[di][4 * jh + dj] + bvp[4 * jh + dj];
                    vp[dj] = x > 0.f ? x : 0.f;
                }
                *(float4*)&orow[64 * jh + 4 * tx] = v;
            }
        }
    }
}

// ---------------- fused 13x13 conv (1->3 ch) + max-pool over 40-row blocks ----------------
// R6 tile shape (proven fastest) + WARP-STAGGERED kc order: warp wid iterates
// kc = (kci + wid) mod 13, so the per-kc LDS dependency stalls of the 4 warps
// sharing an SMSP are offset instead of lock-step. Per-output accumulation
// order is deterministic (wid fixed per output); reassociation is ~1e-7 level.
__global__ __launch_bounds__(256) void conv_pool_kernel(const float* __restrict__ cw,
                                                        const float* __restrict__ cb,
                                                        float* __restrict__ out,
                                                        int ct_base) {
    __shared__ float  s_img[140][52];    // [col][row]
    __shared__ float4 s_w4[169];         // {w_ch0, w_ch1, w_ch2, 0} per (kr*13+kc)
    int ct = blockIdx.x + ct_base, p = blockIdx.y, g = blockIdx.z;
    int tid = threadIdx.x;
    for (int i = tid; i < 169; i += 256)
        s_w4[i] = make_float4(cw[i], cw[169 + i], cw[338 + i], 0.f);

    int base_r = p * 40 - 6, base_c = ct * 128 - 6;
    const float* hg = g_hcat + (size_t)g * NN * SUMH;
    for (int idx = tid; idx < 52 * 140; idx += 256) {
        int r = idx / 140, c = idx - r * 140;
        int gr = base_r + r, gc = base_c + c;
        float v = 0.f;
        if (gr >= 0 && gr < NN && gc >= 0 && gc < SUMH)
            v = hg[(size_t)gr * SUMH + gc];
        s_img[c][r] = v;
    }
    __syncthreads();

    int tx = tid & 127, ty = tid >> 7;
    int wid = tid >> 5;                  // 0..7; SMSP = wid & 3
    int rbase = ty * 20;
    float mx0 = -1e30f, mx1 = -1e30f, mx2 = -1e30f;

    {
        float acc0[20], acc1[20], acc2[20];
        #pragma unroll
        for (int t = 0; t < 20; t++) { acc0[t] = 0.f; acc1[t] = 0.f; acc2[t] = 0.f; }
        #pragma unroll 1
        for (int kci = 0; kci < 13; kci++) {
            int kc = kci + wid;
            if (kc >= 13) kc -= 13;      // rotated, deterministic per warp
            float v[32];
            const float4* vcol = (const float4*)&s_img[tx + kc][rbase];
            #pragma unroll
            for (int q = 0; q < 8; q++) {
                float4 t4 = vcol[q];
                v[4 * q + 0] = t4.x; v[4 * q + 1] = t4.y;
                v[4 * q + 2] = t4.z; v[4 * q + 3] = t4.w;
            }
            #pragma unroll
            for (int kr = 0; kr < 13; kr++) {
                float4 w = s_w4[kr * 13 + kc];
                #pragma unroll
                for (int t = 0; t < 20; t++) {
                    float x = v[kr + t];
                    acc0[t] += x * w.x;
                    acc1[t] += x * w.y;
                    acc2[t] += x * w.z;
                }
            }
        }
        #pragma unroll
        for (int t = 0; t < 20; t++) {
            mx0 = fmaxf(mx0, acc0[t]);
            mx1 = fmaxf(mx1, acc1[t]);
            mx2 = fmaxf(mx2, acc2[t]);
        }
    }

    __syncthreads();                 // done reading s_img; reuse for reduction
    float* red = &s_img[0][0];
    if (ty == 1) { red[tx] = mx0; red[128 + tx] = mx1; red[256 + tx] = mx2; }
    __syncthreads();
    if (ty == 0) {
        mx0 = fmaxf(mx0, red[tx]);
        mx1 = fmaxf(mx1, red[128 + tx]);
        mx2 = fmaxf(mx2, red[256 + tx]);
        int c = ct * 128 + tx;
        out[((size_t)(g * 3 + 0) * 30 + p) * SUMH + c] = mx0 + cb[0];
        out[((size_t)(g * 3 + 1) * 30 + p) * SUMH + c] = mx1 + cb[1];
        out[((size_t)(g * 3 + 2) * 30 + p) * SUMH + c] = mx2 + cb[2];
    }
}

// ---------------- side stream + events (static init; no tracked device allocs) ----------------
struct PipeRes {
    cudaStream_t sc = nullptr;
    cudaEvent_t e1 = nullptr, e2 = nullptr, e3 = nullptr, e4 = nullptr, ej = nullptr;
    PipeRes() {
        cudaStreamCreateWithFlags(&sc, cudaStreamNonBlocking);
        cudaEventCreateWithFlags(&e1, cudaEventDisableTiming);
        cudaEventCreateWithFlags(&e2, cudaEventDisableTiming);
        cudaEventCreateWithFlags(&e3, cudaEventDisableTiming);
        cudaEventCreateWithFlags(&e4, cudaEventDisableTiming);
        cudaEventCreateWithFlags(&ej, cudaEventDisableTiming);
    }
};
static PipeRes g_pipe;

// ---------------- driver ----------------
extern "C" void kernel_launch(void* const* d_in, const int* in_sizes, int n_in,
                              void* d_out, int out_size) {
    const float* feat = (const float*)d_in[0];
    const int*   src  = (const int*)d_in[1];
    const int*   dst  = (const int*)d_in[2];
    const float* W1 = (const float*)d_in[3];  const float* b1 = (const float*)d_in[4];
    const float* W2 = (const float*)d_in[5];  const float* b2 = (const float*)d_in[6];
    const float* W3 = (const float*)d_in[7];  const float* b3 = (const float*)d_in[8];
    const float* W4 = (const float*)d_in[9];  const float* b4 = (const float*)d_in[10];
    const float* cw = (const float*)d_in[11]; const float* cb = (const float*)d_in[12];
    float* out = (float*)d_out;

    cudaStream_t s0 = (cudaStream_t)0;
    cudaStream_t sc = g_pipe.sc;

    build_csr_kernel<<<Gn, 256, 0, s0>>>(src, dst);

    // layer 1
    spmm_kernel<128, false><<<dim3(NN / 8, Gn), 256, 0, s0>>>(feat, 0);
    gemm_kernel<128><<<dim3(19, 2, Gn), 256, 0, s0>>>(W1, b1, 0);
    cudaEventRecord(g_pipe.e1, s0);
    cudaStreamWaitEvent(sc, g_pipe.e1, 0);
    conv_pool_kernel<<<dim3(1, 30, Gn), 256, 0, sc>>>(cw, cb, out, 0);

    // layer 2
    spmm_kernel<256, true><<<dim3(NN / 4, Gn), 256, 0, s0>>>(nullptr, 0);
    gemm_kernel<256><<<dim3(19, 2, Gn), 256, 0, s0>>>(W2, b2, 256);
    cudaEventRecord(g_pipe.e2, s0);
    cudaStreamWaitEvent(sc, g_pipe.e2, 0);
    conv_pool_kernel<<<dim3(2, 30, Gn), 256, 0, sc>>>(cw, cb, out, 1);

    // layer 3
    spmm_kernel<256, true><<<dim3(NN / 4, Gn), 256, 0, s0>>>(nullptr, 256);
    gemm_kernel<256><<<dim3(19, 2, Gn), 256, 0, s0>>>(W3, b3, 512);
    cudaEventRecord(g_pipe.e3, s0);
    cudaStreamWaitEvent(sc, g_pipe.e3, 0);
    conv_pool_kernel<<<dim3(2, 30, Gn), 256, 0, sc>>>(cw, cb, out, 3);

    // layer 4
    spmm_kernel<256, true><<<dim3(NN / 4, Gn), 256, 0, s0>>>(nullptr, 512);
    gemm_kernel<256><<<dim3(19, 2, Gn), 256, 0, s0>>>(W4, b4, 768);
    cudaEventRecord(g_pipe.e4, s0);
    cudaStreamWaitEvent(sc, g_pipe.e4, 0);
    conv_pool_kernel<<<dim3(3, 30, Gn), 256, 0, sc>>>(cw, cb, out, 5);

    // join the fork back into the capture stream
    cudaEventRecord(g_pipe.ej, sc);
    cudaStreamWaitEvent(s0, g_pipe.ej, 0);
}

// round 13
// speedup vs baseline: 1.2942x; 1.1453x over previous
#include <cuda_runtime.h>
#include <cuda_bf16.h>
#include <cstdint>
#include <cstddef>

#define Gn   32
#define NN   1200
#define EE   19200
#define SUMH 1024

// ---------------- static scratch (no cudaMalloc allowed) ----------------
__device__ float g_hcat[(size_t)Gn * NN * SUMH];       // concat(h1..h4), conv input
__device__ uint32_t g_Ahi[(size_t)Gn * NN * 128];      // spmm out, hi bf16 k-pairs
__device__ uint32_t g_Alo[(size_t)Gn * NN * 128];      // spmm out, lo bf16 k-pairs
__device__ uint32_t g_Bhi[4 * 256 * 128];              // W splits, [layer][n][kpair]
__device__ uint32_t g_Blo[4 * 256 * 128];
__device__ int   g_rowptr[Gn * (NN + 1)];
__device__ int   g_esrc[Gn * EE];
__device__ float g_esc[Gn * EE];
__device__ float g_sin[Gn * NN];

__device__ __forceinline__ uint32_t pack_bf16x2(__nv_bfloat16 lo, __nv_bfloat16 hi) {
    return (uint32_t)__bfloat16_as_ushort(hi) << 16 | (uint32_t)__bfloat16_as_ushort(lo);
}
__device__ __forceinline__ void split_bf16(float x, __nv_bfloat16& h, __nv_bfloat16& l) {
    h = __float2bfloat16(x);
    l = __float2bfloat16(x - __bfloat162float(h));
}
__device__ __forceinline__ void mma_bf16(float* c, const uint32_t* a, uint32_t b0, uint32_t b1) {
    asm volatile("mma.sync.aligned.m16n8k16.row.col.f32.bf16.bf16.f32 "
        "{%0,%1,%2,%3}, {%4,%5,%6,%7}, {%8,%9}, {%0,%1,%2,%3};"
        : "+f"(c[0]), "+f"(c[1]), "+f"(c[2]), "+f"(c[3])
        : "r"(a[0]), "r"(a[1]), "r"(a[2]), "r"(a[3]), "r"(b0), "r"(b1));
}

// ---------------- CSR build + degree scales (one CTA per graph) ----------------
__global__ void build_csr_kernel(const int* __restrict__ src, const int* __restrict__ dst) {
    __shared__ int s_in[NN];
    __shared__ int s_out[NN];
    __shared__ int s_ptr[NN + 1];
    int g = blockIdx.x, t = threadIdx.x;
    for (int i = t; i < NN; i += blockDim.x) { s_in[i] = 0; s_out[i] = 0; }
    __syncthreads();
    const int* sg = src + g * EE;
    const int* dg = dst + g * EE;
    for (int e = t; e < EE; e += blockDim.x) {
        atomicAdd(&s_out[sg[e]], 1);
        atomicAdd(&s_in[dg[e]], 1);
    }
    __syncthreads();
    for (int i = t; i < NN; i += blockDim.x) {
        int id = s_in[i] < 1 ? 1 : s_in[i];
        g_sin[g * NN + i] = rsqrtf((float)id);
    }
    if (t == 0) {
        int run = 0;
        for (int i = 0; i < NN; i++) { s_ptr[i] = run; run += s_in[i]; }
        s_ptr[NN] = run;
    }
    __syncthreads();
    for (int i = t; i <= NN; i += blockDim.x) g_rowptr[g * (NN + 1) + i] = s_ptr[i];
    for (int i = t; i < NN; i += blockDim.x) s_in[i] = s_ptr[i];   // write cursors
    __syncthreads();
    for (int e = t; e < EE; e += blockDim.x) {
        int d = dg[e];
        int s = sg[e];
        int pos = atomicAdd(&s_in[d], 1);
        int od = s_out[s] < 1 ? 1 : s_out[s];
        g_esrc[g * EE + pos] = s;
        g_esc[g * EE + pos]  = rsqrtf((float)od);
    }
}

// ---------------- W pre-split: g_B{hi,lo}[l][n][kpair] = packed bf16 pair over k ----------------
__global__ void convert_w_kernel(const float* __restrict__ W1, const float* __restrict__ W2,
                                 const float* __restrict__ W3, const float* __restrict__ W4) {
    int l = blockIdx.y;
    const float* W = (l == 0) ? W1 : (l == 1) ? W2 : (l == 2) ? W3 : W4;
    int K = (l == 0) ? 128 : 256;
    int idx = blockIdx.x * 256 + threadIdx.x;
    if (idx >= 256 * (K / 2)) return;
    int n = idx / (K / 2), kp = idx - n * (K / 2);
    float w0 = W[(size_t)(2 * kp) * 256 + n];
    float w1 = W[(size_t)(2 * kp + 1) * 256 + n];
    __nv_bfloat16 h0, l0, h1, l1;
    split_bf16(w0, h0, l0);
    split_bf16(w1, h1, l1);
    size_t o = (size_t)l * 256 * 128 + (size_t)n * (K / 2) + kp;
    g_Bhi[o] = pack_bf16x2(h0, h1);
    g_Blo[o] = pack_bf16x2(l0, l1);
}

// ---------------- SpMM -> bf16 hi/lo planes ----------------
template <int D, bool FROM_HCAT>
__global__ __launch_bounds__(256) void spmm_kernel(const float* __restrict__ hext, int col_off) {
    constexpr int LPN = D / 4;
    constexpr int NPB = 256 / LPN;
    int g = blockIdx.y;
    int lane = threadIdx.x & (LPN - 1);
    int ni   = threadIdx.x / LPN;
    int v = blockIdx.x * NPB + ni;

    const int* rp = g_rowptr + g * (NN + 1);
    int beg = rp[v], end = rp[v + 1];
    const int*   es  = g_esrc + g * EE;
    const float* esc = g_esc  + g * EE;

    float4 acc = make_float4(0.f, 0.f, 0.f, 0.f);
    const float* base;
    size_t rstride;
    if (FROM_HCAT) { base = g_hcat + (size_t)g * NN * SUMH + col_off + 4 * lane; rstride = SUMH; }
    else           { base = hext   + (size_t)g * NN * D    + 4 * lane;           rstride = D;    }

    #pragma unroll 4
    for (int e = beg; e < end; e++) {
        int s = es[e];
        float sc = esc[e];
        float4 hv = *(const float4*)(base + (size_t)s * rstride);
        acc.x += hv.x * sc; acc.y += hv.y * sc;
        acc.z += hv.z * sc; acc.w += hv.w * sc;
    }
    float si = g_sin[g * NN + v];
    float va[4] = {acc.x * si, acc.y * si, acc.z * si, acc.w * si};
    __nv_bfloat16 h[4], l[4];
    #pragma unroll
    for (int j = 0; j < 4; j++) split_bf16(va[j], h[j], l[j]);
    size_t o32 = ((size_t)g * NN + v) * (D / 2) + 2 * lane;   // uint32 index
    *(uint2*)&g_Ahi[o32] = make_uint2(pack_bf16x2(h[0], h[1]), pack_bf16x2(h[2], h[3]));
    *(uint2*)&g_Alo[o32] = make_uint2(pack_bf16x2(l[0], l[1]), pack_bf16x2(l[2], l[3]));
}

// ---------------- tensor-core GEMM (mma.sync bf16x2 split) + bias + ReLU ----------------
// h = relu(A @ W + b). CTA 128x128, BK=16 (8 kpairs/chunk), 8 warps (4M x 2N),
// warp tile 32x64. All bf16 splits precomputed (spmm epilogue / convert_w).
// D = Ahi*Bhi + Ahi*Blo + Alo*Bhi in fp32 accumulators.
template <int K>
__global__ __launch_bounds__(256) void gemm_tc_kernel(int layer,
                                                      const float* __restrict__ bias,
                                                      int col_off) {
    __shared__ uint32_t Ah[8][136], Al[8][136], Bh[8][136], Bl[8][136];
    constexpr int KP = K / 2;          // kpairs per row
    constexpr int NCH = K / 16;        // chunks
    int g = blockIdx.z;
    int m0 = blockIdx.x * 128, n0 = blockIdx.y * 128;
    int tid = threadIdx.x;
    int lane = tid & 31, wid = tid >> 5;
    int wm = wid & 3, wn = wid >> 2;
    int gid = lane >> 2, tig = lane & 3;

    float acc[2][8][4];
    #pragma unroll
    for (int mi = 0; mi < 2; mi++)
        #pragma unroll
        for (int nj = 0; nj < 8; nj++)
            #pragma unroll
            for (int q = 0; q < 4; q++) acc[mi][nj][q] = 0.f;

    const uint32_t* gAhp = g_Ahi + (size_t)g * NN * KP;
    const uint32_t* gAlp = g_Alo + (size_t)g * NN * KP;
    const uint32_t* gBhp = g_Bhi + (size_t)layer * 256 * 128;
    const uint32_t* gBlp = g_Blo + (size_t)layer * 256 * 128;

    int lrow = tid >> 1;               // 0..127 (m or n within tile)
    int kpb  = (tid & 1) * 4;          // kpair base 0 or 4
    bool a_ok = (m0 + lrow) < NN;

    uint4 rah, ral, rbh, rbl;
    {
        if (a_ok) {
            rah = *(const uint4*)&gAhp[(size_t)(m0 + lrow) * KP + kpb];
            ral = *(const uint4*)&gAlp[(size_t)(m0 + lrow) * KP + kpb];
        } else { rah = make_uint4(0, 0, 0, 0); ral = rah; }
        rbh = *(const uint4*)&gBhp[(size_t)(n0 + lrow) * KP + kpb];
        rbl = *(const uint4*)&gBlp[(size_t)(n0 + lrow) * KP + kpb];
    }

    for (int ch = 0; ch < NCH; ch++) {
        Ah[kpb + 0][lrow] = rah.x; Ah[kpb + 1][lrow] = rah.y;
        Ah[kpb + 2][lrow] = rah.z; Ah[kpb + 3][lrow] = rah.w;
        Al[kpb + 0][lrow] = ral.x; Al[kpb + 1][lrow] = ral.y;
        Al[kpb + 2][lrow] = ral.z; Al[kpb + 3][lrow] = ral.w;
        Bh[kpb + 0][lrow] = rbh.x; Bh[kpb + 1][lrow] = rbh.y;
        Bh[kpb + 2][lrow] = rbh.z; Bh[kpb + 3][lrow] = rbh.w;
        Bl[kpb + 0][lrow] = rbl.x; Bl[kpb + 1][lrow] = rbl.y;
        Bl[kpb + 2][lrow] = rbl.z; Bl[kpb + 3][lrow] = rbl.w;
        __syncthreads();

        if (ch + 1 < NCH) {
            int kq = (ch + 1) * 8 + kpb;
            if (a_ok) {
                rah = *(const uint4*)&gAhp[(size_t)(m0 + lrow) * KP + kq];
                ral = *(const uint4*)&gAlp[(size_t)(m0 + lrow) * KP + kq];
            }
            rbh = *(const uint4*)&gBhp[(size_t)(n0 + lrow) * KP + kq];
            rbl = *(const uint4*)&gBlp[(size_t)(n0 + lrow) * KP + kq];
        }

        uint32_t ah[2][4], al[2][4];
        #pragma unroll
        for (int mi = 0; mi < 2; mi++) {
            int m = wm * 32 + mi * 16 + gid;
            ah[mi][0] = Ah[tig][m];     ah[mi][1] = Ah[tig][m + 8];
            ah[mi][2] = Ah[tig + 4][m]; ah[mi][3] = Ah[tig + 4][m + 8];
            al[mi][0] = Al[tig][m];     al[mi][1] = Al[tig][m + 8];
            al[mi][2] = Al[tig + 4][m]; al[mi][3] = Al[tig + 4][m + 8];
        }
        #pragma unroll
        for (int nj = 0; nj < 8; nj++) {
            int n = wn * 64 + nj * 8 + gid;
            uint32_t bh0 = Bh[tig][n], bh1 = Bh[tig + 4][n];
            uint32_t bl0 = Bl[tig][n], bl1 = Bl[tig + 4][n];
            #pragma unroll
            for (int mi = 0; mi < 2; mi++) {
                mma_bf16(acc[mi][nj], ah[mi], bh0, bh1);   // hi*hi
                mma_bf16(acc[mi][nj], ah[mi], bl0, bl1);   // hi*lo
                mma_bf16(acc[mi][nj], al[mi], bh0, bh1);   // lo*hi
            }
        }
        __syncthreads();
    }

    // epilogue: bias + relu (c0,c1 -> row gid, cols 2tig,2tig+1; c2,c3 -> row gid+8)
    #pragma unroll
    for (int nj = 0; nj < 8; nj++) {
        int c = n0 + wn * 64 + nj * 8 + 2 * tig;
        float2 bb = *(const float2*)&bias[c];
        #pragma unroll
        for (int mi = 0; mi < 2; mi++) {
            int r0 = m0 + wm * 32 + mi * 16 + gid;
            int r1 = r0 + 8;
            if (r0 < NN) {
                float vx = acc[mi][nj][0] + bb.x;
                float vy = acc[mi][nj][1] + bb.y;
                float2 v = make_float2(vx > 0.f ? vx : 0.f, vy > 0.f ? vy : 0.f);
                *(float2*)&g_hcat[((size_t)g * NN + r0) * SUMH + col_off + c] = v;
            }
            if (r1 < NN) {
                float vx = acc[mi][nj][2] + bb.x;
                float vy = acc[mi][nj][3] + bb.y;
                float2 v = make_float2(vx > 0.f ? vx : 0.f, vy > 0.f ? vy : 0.f);
                *(float2*)&g_hcat[((size_t)g * NN + r1) * SUMH + col_off + c] = v;
            }
        }
    }
}

// ---------------- fused 13x13 conv (1->3 ch) + max-pool (R11 winner, unchanged) ----------------
__global__ __launch_bounds__(256) void conv_pool_kernel(const float* __restrict__ cw,
                                                        const float* __restrict__ cb,
                                                        float* __restrict__ out,
                                                        int ct_base) {
    __shared__ float  s_img[140][52];
    __shared__ float4 s_w4[169];
    int ct = blockIdx.x + ct_base, p = blockIdx.y, g = blockIdx.z;
    int tid = threadIdx.x;
    for (int i = tid; i < 169; i += 256)
        s_w4[i] = make_float4(cw[i], cw[169 + i], cw[338 + i], 0.f);

    int base_r = p * 40 - 6, base_c = ct * 128 - 6;
    const float* hg = g_hcat + (size_t)g * NN * SUMH;
    for (int idx = tid; idx < 52 * 140; idx += 256) {
        int r = idx / 140, c = idx - r * 140;
        int gr = base_r + r, gc = base_c + c;
        float v = 0.f;
        if (gr >= 0 && gr < NN && gc >= 0 && gc < SUMH)
            v = hg[(size_t)gr * SUMH + gc];
        s_img[c][r] = v;
    }
    __syncthreads();

    int tx = tid & 127, ty = tid >> 7;
    int wid = tid >> 5;
    int rbase = ty * 20;
    float mx0 = -1e30f, mx1 = -1e30f, mx2 = -1e30f;

    {
        float acc0[20], acc1[20], acc2[20];
        #pragma unroll
        for (int t = 0; t < 20; t++) { acc0[t] = 0.f; acc1[t] = 0.f; acc2[t] = 0.f; }
        #pragma unroll 1
        for (int kci = 0; kci < 13; kci++) {
            int kc = kci + wid;
            if (kc >= 13) kc -= 13;
            float v[32];
            const float4* vcol = (const float4*)&s_img[tx + kc][rbase];
            #pragma unroll
            for (int q = 0; q < 8; q++) {
                float4 t4 = vcol[q];
                v[4 * q + 0] = t4.x; v[4 * q + 1] = t4.y;
                v[4 * q + 2] = t4.z; v[4 * q + 3] = t4.w;
            }
            #pragma unroll
            for (int kr = 0; kr < 13; kr++) {
                float4 w = s_w4[kr * 13 + kc];
                #pragma unroll
                for (int t = 0; t < 20; t++) {
                    float x = v[kr + t];
                    acc0[t] += x * w.x;
                    acc1[t] += x * w.y;
                    acc2[t] += x * w.z;
                }
            }
        }
        #pragma unroll
        for (int t = 0; t < 20; t++) {
            mx0 = fmaxf(mx0, acc0[t]);
            mx1 = fmaxf(mx1, acc1[t]);
            mx2 = fmaxf(mx2, acc2[t]);
        }
    }

    __syncthreads();
    float* red = &s_img[0][0];
    if (ty == 1) { red[tx] = mx0; red[128 + tx] = mx1; red[256 + tx] = mx2; }
    __syncthreads();
    if (ty == 0) {
        mx0 = fmaxf(mx0, red[tx]);
        mx1 = fmaxf(mx1, red[128 + tx]);
        mx2 = fmaxf(mx2, red[256 + tx]);
        int c = ct * 128 + tx;
        out[((size_t)(g * 3 + 0) * 30 + p) * SUMH + c] = mx0 + cb[0];
        out[((size_t)(g * 3 + 1) * 30 + p) * SUMH + c] = mx1 + cb[1];
        out[((size_t)(g * 3 + 2) * 30 + p) * SUMH + c] = mx2 + cb[2];
    }
}

// ---------------- side stream + events (static init; no tracked device allocs) ----------------
struct PipeRes {
    cudaStream_t sc = nullptr;
    cudaEvent_t e1 = nullptr, e2 = nullptr, e3 = nullptr, e4 = nullptr, ej = nullptr;
    PipeRes() {
        cudaStreamCreateWithFlags(&sc, cudaStreamNonBlocking);
        cudaEventCreateWithFlags(&e1, cudaEventDisableTiming);
        cudaEventCreateWithFlags(&e2, cudaEventDisableTiming);
        cudaEventCreateWithFlags(&e3, cudaEventDisableTiming);
        cudaEventCreateWithFlags(&e4, cudaEventDisableTiming);
        cudaEventCreateWithFlags(&ej, cudaEventDisableTiming);
    }
};
static PipeRes g_pipe;

// ---------------- driver ----------------
extern "C" void kernel_launch(void* const* d_in, const int* in_sizes, int n_in,
                              void* d_out, int out_size) {
    const float* feat = (const float*)d_in[0];
    const int*   src  = (const int*)d_in[1];
    const int*   dst  = (const int*)d_in[2];
    const float* W1 = (const float*)d_in[3];  const float* b1 = (const float*)d_in[4];
    const float* W2 = (const float*)d_in[5];  const float* b2 = (const float*)d_in[6];
    const float* W3 = (const float*)d_in[7];  const float* b3 = (const float*)d_in[8];
    const float* W4 = (const float*)d_in[9];  const float* b4 = (const float*)d_in[10];
    const float* cw = (const float*)d_in[11]; const float* cb = (const float*)d_in[12];
    float* out = (float*)d_out;

    cudaStream_t s0 = (cudaStream_t)0;
    cudaStream_t sc = g_pipe.sc;

    convert_w_kernel<<<dim3(128, 4), 256, 0, s0>>>(W1, W2, W3, W4);
    build_csr_kernel<<<Gn, 256, 0, s0>>>(src, dst);

    // layer 1
    spmm_kernel<128, false><<<dim3(NN / 8, Gn), 256, 0, s0>>>(feat, 0);
    gemm_tc_kernel<128><<<dim3(10, 2, Gn), 256, 0, s0>>>(0, b1, 0);
    cudaEventRecord(g_pipe.e1, s0);
    cudaStreamWaitEvent(sc, g_pipe.e1, 0);
    conv_pool_kernel<<<dim3(1, 30, Gn), 256, 0, sc>>>(cw, cb, out, 0);

    // layer 2
    spmm_kernel<256, true><<<dim3(NN / 4, Gn), 256, 0, s0>>>(nullptr, 0);
    gemm_tc_kernel<256><<<dim3(10, 2, Gn), 256, 0, s0>>>(1, b2, 256);
    cudaEventRecord(g_pipe.e2, s0);
    cudaStreamWaitEvent(sc, g_pipe.e2, 0);
    conv_pool_kernel<<<dim3(2, 30, Gn), 256, 0, sc>>>(cw, cb, out, 1);

    // layer 3
    spmm_kernel<256, true><<<dim3(NN / 4, Gn), 256, 0, s0>>>(nullptr, 256);
    gemm_tc_kernel<256><<<dim3(10, 2, Gn), 256, 0, s0>>>(2, b3, 512);
    cudaEventRecord(g_pipe.e3, s0);
    cudaStreamWaitEvent(sc, g_pipe.e3, 0);
    conv_pool_kernel<<<dim3(2, 30, Gn), 256, 0, sc>>>(cw, cb, out, 3);

    // layer 4
    spmm_kernel<256, true><<<dim3(NN / 4, Gn), 256, 0, s0>>>(nullptr, 512);
    gemm_tc_kernel<256><<<dim3(10, 2, Gn), 256, 0, s0>>>(3, b4, 768);
    cudaEventRecord(g_pipe.e4, s0);
    cudaStreamWaitEvent(sc, g_pipe.e4, 0);
    conv_pool_kernel<<<dim3(3, 30, Gn), 256, 0, sc>>>(cw, cb, out, 5);

    // join the fork back into the capture stream
    cudaEventRecord(g_pipe.ej, sc);
    cudaStreamWaitEvent(s0, g_pipe.ej, 0);
}

// round 14
// speedup vs baseline: 1.2987x; 1.0035x over previous
#include <cuda_runtime.h>
#include <cuda_bf16.h>
#include <cstdint>
#include <cstddef>

#define Gn   32
#define NN   1200
#define EE   19200
#define SUMH 1024

// ---------------- static scratch (no cudaMalloc allowed) ----------------
__device__ float g_hcat[(size_t)Gn * NN * SUMH];       // concat(h1..h4), conv input
__device__ uint32_t g_Ahi[(size_t)Gn * NN * 128];      // spmm out, hi bf16 k-pairs
__device__ uint32_t g_Alo[(size_t)Gn * NN * 128];      // spmm out, lo bf16 k-pairs
__device__ uint32_t g_Bhi[4 * 256 * 128];              // W splits, [layer][n][kpair]
__device__ uint32_t g_Blo[4 * 256 * 128];
__device__ int   g_rowptr[Gn * (NN + 1)];
__device__ int   g_esrc[Gn * EE];
__device__ float g_esc[Gn * EE];
__device__ float g_sin[Gn * NN];

__device__ __forceinline__ uint32_t pack_bf16x2(__nv_bfloat16 lo, __nv_bfloat16 hi) {
    return (uint32_t)__bfloat16_as_ushort(hi) << 16 | (uint32_t)__bfloat16_as_ushort(lo);
}
__device__ __forceinline__ void split_bf16(float x, __nv_bfloat16& h, __nv_bfloat16& l) {
    h = __float2bfloat16(x);
    l = __float2bfloat16(x - __bfloat162float(h));
}
__device__ __forceinline__ void mma_bf16(float* c, const uint32_t* a, uint32_t b0, uint32_t b1) {
    asm volatile("mma.sync.aligned.m16n8k16.row.col.f32.bf16.bf16.f32 "
        "{%0,%1,%2,%3}, {%4,%5,%6,%7}, {%8,%9}, {%0,%1,%2,%3};"
        : "+f"(c[0]), "+f"(c[1]), "+f"(c[2]), "+f"(c[3])
        : "r"(a[0]), "r"(a[1]), "r"(a[2]), "r"(a[3]), "r"(b0), "r"(b1));
}

// ---------------- CSR build + degree scales (one CTA per graph) ----------------
__global__ void build_csr_kernel(const int* __restrict__ src, const int* __restrict__ dst) {
    __shared__ int s_in[NN];
    __shared__ int s_out[NN];
    __shared__ int s_ptr[NN + 1];
    int g = blockIdx.x, t = threadIdx.x;
    for (int i = t; i < NN; i += blockDim.x) { s_in[i] = 0; s_out[i] = 0; }
    __syncthreads();
    const int* sg = src + g * EE;
    const int* dg = dst + g * EE;
    for (int e = t; e < EE; e += blockDim.x) {
        atomicAdd(&s_out[sg[e]], 1);
        atomicAdd(&s_in[dg[e]], 1);
    }
    __syncthreads();
    for (int i = t; i < NN; i += blockDim.x) {
        int id = s_in[i] < 1 ? 1 : s_in[i];
        g_sin[g * NN + i] = rsqrtf((float)id);
    }
    if (t == 0) {
        int run = 0;
        for (int i = 0; i < NN; i++) { s_ptr[i] = run; run += s_in[i]; }
        s_ptr[NN] = run;
    }
    __syncthreads();
    for (int i = t; i <= NN; i += blockDim.x) g_rowptr[g * (NN + 1) + i] = s_ptr[i];
    for (int i = t; i < NN; i += blockDim.x) s_in[i] = s_ptr[i];   // write cursors
    __syncthreads();
    for (int e = t; e < EE; e += blockDim.x) {
        int d = dg[e];
        int s = sg[e];
        int pos = atomicAdd(&s_in[d], 1);
        int od = s_out[s] < 1 ? 1 : s_out[s];
        g_esrc[g * EE + pos] = s;
        g_esc[g * EE + pos]  = rsqrtf((float)od);
    }
}

// ---------------- W pre-split: g_B{hi,lo}[l][n][kpair] = packed bf16 pair over k ----------------
__global__ void convert_w_kernel(const float* __restrict__ W1, const float* __restrict__ W2,
                                 const float* __restrict__ W3, const float* __restrict__ W4) {
    int l = blockIdx.y;
    const float* W = (l == 0) ? W1 : (l == 1) ? W2 : (l == 2) ? W3 : W4;
    int K = (l == 0) ? 128 : 256;
    int idx = blockIdx.x * 256 + threadIdx.x;
    if (idx >= 256 * (K / 2)) return;
    int n = idx / (K / 2), kp = idx - n * (K / 2);
    float w0 = W[(size_t)(2 * kp) * 256 + n];
    float w1 = W[(size_t)(2 * kp + 1) * 256 + n];
    __nv_bfloat16 h0, l0, h1, l1;
    split_bf16(w0, h0, l0);
    split_bf16(w1, h1, l1);
    size_t o = (size_t)l * 256 * 128 + (size_t)n * (K / 2) + kp;
    g_Bhi[o] = pack_bf16x2(h0, h1);
    g_Blo[o] = pack_bf16x2(l0, l1);
}

// ---------------- SpMM -> bf16 hi/lo planes ----------------
template <int D, bool FROM_HCAT>
__global__ __launch_bounds__(256) void spmm_kernel(const float* __restrict__ hext, int col_off) {
    constexpr int LPN = D / 4;
    constexpr int NPB = 256 / LPN;
    int g = blockIdx.y;
    int lane = threadIdx.x & (LPN - 1);
    int ni   = threadIdx.x / LPN;
    int v = blockIdx.x * NPB + ni;

    const int* rp = g_rowptr + g * (NN + 1);
    int beg = rp[v], end = rp[v + 1];
    const int*   es  = g_esrc + g * EE;
    const float* esc = g_esc  + g * EE;

    float4 acc = make_float4(0.f, 0.f, 0.f, 0.f);
    const float* base;
    size_t rstride;
    if (FROM_HCAT) { base = g_hcat + (size_t)g * NN * SUMH + col_off + 4 * lane; rstride = SUMH; }
    else           { base = hext   + (size_t)g * NN * D    + 4 * lane;           rstride = D;    }

    #pragma unroll 4
    for (int e = beg; e < end; e++) {
        int s = es[e];
        float sc = esc[e];
        float4 hv = *(const float4*)(base + (size_t)s * rstride);
        acc.x += hv.x * sc; acc.y += hv.y * sc;
        acc.z += hv.z * sc; acc.w += hv.w * sc;
    }
    float si = g_sin[g * NN + v];
    float va[4] = {acc.x * si, acc.y * si, acc.z * si, acc.w * si};
    __nv_bfloat16 h[4], l[4];
    #pragma unroll
    for (int j = 0; j < 4; j++) split_bf16(va[j], h[j], l[j]);
    size_t o32 = ((size_t)g * NN + v) * (D / 2) + 2 * lane;   // uint32 index
    *(uint2*)&g_Ahi[o32] = make_uint2(pack_bf16x2(h[0], h[1]), pack_bf16x2(h[2], h[3]));
    *(uint2*)&g_Alo[o32] = make_uint2(pack_bf16x2(l[0], l[1]), pack_bf16x2(l[2], l[3]));
}

// ---------------- tensor-core GEMM (mma.sync bf16x2 split, ping-pong smem) ----------------
// h = relu(A @ W + b). CTA 128x128, BK=16 (8 kpairs/chunk), 8 warps (4M x 2N),
// warp tile 32x64. Double-buffered smem: ONE __syncthreads per chunk; chunk-i
// MMAs overlap chunk-i+1 global loads + smem stores (different buffer parity).
template <int K>
__global__ __launch_bounds__(256) void gemm_tc_kernel(int layer,
                                                      const float* __restrict__ bias,
                                                      int col_off) {
    __shared__ uint32_t Ah[2][8][136], Al[2][8][136], Bh[2][8][136], Bl[2][8][136];
    constexpr int KP = K / 2;          // kpairs per row
    constexpr int NCH = K / 16;        // chunks
    int g = blockIdx.z;
    int m0 = blockIdx.x * 128, n0 = blockIdx.y * 128;
    int tid = threadIdx.x;
    int lane = tid & 31, wid = tid >> 5;
    int wm = wid & 3, wn = wid >> 2;
    int gid = lane >> 2, tig = lane & 3;

    float acc[2][8][4];
    #pragma unroll
    for (int mi = 0; mi < 2; mi++)
        #pragma unroll
        for (int nj = 0; nj < 8; nj++)
            #pragma unroll
            for (int q = 0; q < 4; q++) acc[mi][nj][q] = 0.f;

    const uint32_t* gAhp = g_Ahi + (size_t)g * NN * KP;
    const uint32_t* gAlp = g_Alo + (size_t)g * NN * KP;
    const uint32_t* gBhp = g_Bhi + (size_t)layer * 256 * 128;
    const uint32_t* gBlp = g_Blo + (size_t)layer * 256 * 128;

    int lrow = tid >> 1;               // 0..127 (m or n within tile)
    int kpb  = (tid & 1) * 4;          // kpair base 0 or 4
    bool a_ok = (m0 + lrow) < NN;

    uint4 rah, ral, rbh, rbl;
    // prefetch + store chunk 0 into buffer 0
    {
        if (a_ok) {
            rah = *(const uint4*)&gAhp[(size_t)(m0 + lrow) * KP + kpb];
            ral = *(const uint4*)&gAlp[(size_t)(m0 + lrow) * KP + kpb];
        } else { rah = make_uint4(0, 0, 0, 0); ral = rah; }
        rbh = *(const uint4*)&gBhp[(size_t)(n0 + lrow) * KP + kpb];
        rbl = *(const uint4*)&gBlp[(size_t)(n0 + lrow) * KP + kpb];
        Ah[0][kpb + 0][lrow] = rah.x; Ah[0][kpb + 1][lrow] = rah.y;
        Ah[0][kpb + 2][lrow] = rah.z; Ah[0][kpb + 3][lrow] = rah.w;
        Al[0][kpb + 0][lrow] = ral.x; Al[0][kpb + 1][lrow] = ral.y;
        Al[0][kpb + 2][lrow] = ral.z; Al[0][kpb + 3][lrow] = ral.w;
        Bh[0][kpb + 0][lrow] = rbh.x; Bh[0][kpb + 1][lrow] = rbh.y;
        Bh[0][kpb + 2][lrow] = rbh.z; Bh[0][kpb + 3][lrow] = rbh.w;
        Bl[0][kpb + 0][lrow] = rbl.x; Bl[0][kpb + 1][lrow] = rbl.y;
        Bl[0][kpb + 2][lrow] = rbl.z; Bl[0][kpb + 3][lrow] = rbl.w;
    }
    __syncthreads();

    for (int ch = 0; ch < NCH; ch++) {
        int cur = ch & 1, nxt = cur ^ 1;
        bool have_next = (ch + 1) < NCH;
        if (have_next) {
            int kq = (ch + 1) * 8 + kpb;
            if (a_ok) {
                rah = *(const uint4*)&gAhp[(size_t)(m0 + lrow) * KP + kq];
                ral = *(const uint4*)&gAlp[(size_t)(m0 + lrow) * KP + kq];
            }
            rbh = *(const uint4*)&gBhp[(size_t)(n0 + lrow) * KP + kq];
            rbl = *(const uint4*)&gBlp[(size_t)(n0 + lrow) * KP + kq];
        }

        uint32_t ah[2][4], al[2][4];
        #pragma unroll
        for (int mi = 0; mi < 2; mi++) {
            int m = wm * 32 + mi * 16 + gid;
            ah[mi][0] = Ah[cur][tig][m];     ah[mi][1] = Ah[cur][tig][m + 8];
            ah[mi][2] = Ah[cur][tig + 4][m]; ah[mi][3] = Ah[cur][tig + 4][m + 8];
            al[mi][0] = Al[cur][tig][m];     al[mi][1] = Al[cur][tig][m + 8];
            al[mi][2] = Al[cur][tig + 4][m]; al[mi][3] = Al[cur][tig + 4][m + 8];
        }
        #pragma unroll
        for (int nj = 0; nj < 8; nj++) {
            int n = wn * 64 + nj * 8 + gid;
            uint32_t bh0 = Bh[cur][tig][n], bh1 = Bh[cur][tig + 4][n];
            uint32_t bl0 = Bl[cur][tig][n], bl1 = Bl[cur][tig + 4][n];
            #pragma unroll
            for (int mi = 0; mi < 2; mi++) {
                mma_bf16(acc[mi][nj], ah[mi], bh0, bh1);   // hi*hi
                mma_bf16(acc[mi][nj], ah[mi], bl0, bl1);   // hi*lo
                mma_bf16(acc[mi][nj], al[mi], bh0, bh1);   // lo*hi
            }
        }

        if (have_next) {
            Ah[nxt][kpb + 0][lrow] = rah.x; Ah[nxt][kpb + 1][lrow] = rah.y;
            Ah[nxt][kpb + 2][lrow] = rah.z; Ah[nxt][kpb + 3][lrow] = rah.w;
            Al[nxt][kpb + 0][lrow] = ral.x; Al[nxt][kpb + 1][lrow] = ral.y;
            Al[nxt][kpb + 2][lrow] = ral.z; Al[nxt][kpb + 3][lrow] = ral.w;
            Bh[nxt][kpb + 0][lrow] = rbh.x; Bh[nxt][kpb + 1][lrow] = rbh.y;
            Bh[nxt][kpb + 2][lrow] = rbh.z; Bh[nxt][kpb + 3][lrow] = rbh.w;
            Bl[nxt][kpb + 0][lrow] = rbl.x; Bl[nxt][kpb + 1][lrow] = rbl.y;
            Bl[nxt][kpb + 2][lrow] = rbl.z; Bl[nxt][kpb + 3][lrow] = rbl.w;
            __syncthreads();
        }
    }

    // epilogue: bias + relu (c0,c1 -> row gid, cols 2tig,2tig+1; c2,c3 -> row gid+8)
    #pragma unroll
    for (int nj = 0; nj < 8; nj++) {
        int c = n0 + wn * 64 + nj * 8 + 2 * tig;
        float2 bb = *(const float2*)&bias[c];
        #pragma unroll
        for (int mi = 0; mi < 2; mi++) {
            int r0 = m0 + wm * 32 + mi * 16 + gid;
            int r1 = r0 + 8;
            if (r0 < NN) {
                float vx = acc[mi][nj][0] + bb.x;
                float vy = acc[mi][nj][1] + bb.y;
                float2 v = make_float2(vx > 0.f ? vx : 0.f, vy > 0.f ? vy : 0.f);
                *(float2*)&g_hcat[((size_t)g * NN + r0) * SUMH + col_off + c] = v;
            }
            if (r1 < NN) {
                float vx = acc[mi][nj][2] + bb.x;
                float vy = acc[mi][nj][3] + bb.y;
                float2 v = make_float2(vx > 0.f ? vx : 0.f, vy > 0.f ? vy : 0.f);
                *(float2*)&g_hcat[((size_t)g * NN + r1) * SUMH + col_off + c] = v;
            }
        }
    }
}

// ---------------- fused 13x13 conv (1->3 ch) + max-pool (R11 winner, unchanged) ----------------
__global__ __launch_bounds__(256) void conv_pool_kernel(const float* __restrict__ cw,
                                                        const float* __restrict__ cb,
                                                        float* __restrict__ out,
                                                        int ct_base) {
    __shared__ float  s_img[140][52];
    __shared__ float4 s_w4[169];
    int ct = blockIdx.x + ct_base, p = blockIdx.y, g = blockIdx.z;
    int tid = threadIdx.x;
    for (int i = tid; i < 169; i += 256)
        s_w4[i] = make_float4(cw[i], cw[169 + i], cw[338 + i], 0.f);

    int base_r = p * 40 - 6, base_c = ct * 128 - 6;
    const float* hg = g_hcat + (size_t)g * NN * SUMH;
    for (int idx = tid; idx < 52 * 140; idx += 256) {
        int r = idx / 140, c = idx - r * 140;
        int gr = base_r + r, gc = base_c + c;
        float v = 0.f;
        if (gr >= 0 && gr < NN && gc >= 0 && gc < SUMH)
            v = hg[(size_t)gr * SUMH + gc];
        s_img[c][r] = v;
    }
    __syncthreads();

    int tx = tid & 127, ty = tid >> 7;
    int wid = tid >> 5;
    int rbase = ty * 20;
    float mx0 = -1e30f, mx1 = -1e30f, mx2 = -1e30f;

    {
        float acc0[20], acc1[20], acc2[20];
        #pragma unroll
        for (int t = 0; t < 20; t++) { acc0[t] = 0.f; acc1[t] = 0.f; acc2[t] = 0.f; }
        #pragma unroll 1
        for (int kci = 0; kci < 13; kci++) {
            int kc = kci + wid;
            if (kc >= 13) kc -= 13;
            float v[32];
            const float4* vcol = (const float4*)&s_img[tx + kc][rbase];
            #pragma unroll
            for (int q = 0; q < 8; q++) {
                float4 t4 = vcol[q];
                v[4 * q + 0] = t4.x; v[4 * q + 1] = t4.y;
                v[4 * q + 2] = t4.z; v[4 * q + 3] = t4.w;
            }
            #pragma unroll
            for (int kr = 0; kr < 13; kr++) {
                float4 w = s_w4[kr * 13 + kc];
                #pragma unroll
                for (int t = 0; t < 20; t++) {
                    float x = v[kr + t];
                    acc0[t] += x * w.x;
                    acc1[t] += x * w.y;
                    acc2[t] += x * w.z;
                }
            }
        }
        #pragma unroll
        for (int t = 0; t < 20; t++) {
            mx0 = fmaxf(mx0, acc0[t]);
            mx1 = fmaxf(mx1, acc1[t]);
            mx2 = fmaxf(mx2, acc2[t]);
        }
    }

    __syncthreads();
    float* red = &s_img[0][0];
    if (ty == 1) { red[tx] = mx0; red[128 + tx] = mx1; red[256 + tx] = mx2; }
    __syncthreads();
    if (ty == 0) {
        mx0 = fmaxf(mx0, red[tx]);
        mx1 = fmaxf(mx1, red[128 + tx]);
        mx2 = fmaxf(mx2, red[256 + tx]);
        int c = ct * 128 + tx;
        out[((size_t)(g * 3 + 0) * 30 + p) * SUMH + c] = mx0 + cb[0];
        out[((size_t)(g * 3 + 1) * 30 + p) * SUMH + c] = mx1 + cb[1];
        out[((size_t)(g * 3 + 2) * 30 + p) * SUMH + c] = mx2 + cb[2];
    }
}

// ---------------- side stream + events (static init; no tracked device allocs) ----------------
struct PipeRes {
    cudaStream_t sc = nullptr;
    cudaEvent_t e1 = nullptr, e2 = nullptr, e3 = nullptr, e4 = nullptr, ej = nullptr;
    PipeRes() {
        cudaStreamCreateWithFlags(&sc, cudaStreamNonBlocking);
        cudaEventCreateWithFlags(&e1, cudaEventDisableTiming);
        cudaEventCreateWithFlags(&e2, cudaEventDisableTiming);
        cudaEventCreateWithFlags(&e3, cudaEventDisableTiming);
        cudaEventCreateWithFlags(&e4, cudaEventDisableTiming);
        cudaEventCreateWithFlags(&ej, cudaEventDisableTiming);
    }
};
static PipeRes g_pipe;

// ---------------- driver ----------------
extern "C" void kernel_launch(void* const* d_in, const int* in_sizes, int n_in,
                              void* d_out, int out_size) {
    const float* feat = (const float*)d_in[0];
    const int*   src  = (const int*)d_in[1];
    const int*   dst  = (const int*)d_in[2];
    const float* W1 = (const float*)d_in[3];  const float* b1 = (const float*)d_in[4];
    const float* W2 = (const float*)d_in[5];  const float* b2 = (const float*)d_in[6];
    const float* W3 = (const float*)d_in[7];  const float* b3 = (const float*)d_in[8];
    const float* W4 = (const float*)d_in[9];  const float* b4 = (const float*)d_in[10];
    const float* cw = (const float*)d_in[11]; const float* cb = (const float*)d_in[12];
    float* out = (float*)d_out;

    cudaStream_t s0 = (cudaStream_t)0;
    cudaStream_t sc = g_pipe.sc;

    convert_w_kernel<<<dim3(128, 4), 256, 0, s0>>>(W1, W2, W3, W4);
    build_csr_kernel<<<Gn, 256, 0, s0>>>(src, dst);

    // layer 1
    spmm_kernel<128, false><<<dim3(NN / 8, Gn), 256, 0, s0>>>(feat, 0);
    gemm_tc_kernel<128><<<dim3(10, 2, Gn), 256, 0, s0>>>(0, b1, 0);
    cudaEventRecord(g_pipe.e1, s0);
    cudaStreamWaitEvent(sc, g_pipe.e1, 0);
    conv_pool_kernel<<<dim3(1, 30, Gn), 256, 0, sc>>>(cw, cb, out, 0);

    // layer 2
    spmm_kernel<256, true><<<dim3(NN / 4, Gn), 256, 0, s0>>>(nullptr, 0);
    gemm_tc_kernel<256><<<dim3(10, 2, Gn), 256, 0, s0>>>(1, b2, 256);
    cudaEventRecord(g_pipe.e2, s0);
    cudaStreamWaitEvent(sc, g_pipe.e2, 0);
    conv_pool_kernel<<<dim3(2, 30, Gn), 256, 0, sc>>>(cw, cb, out, 1);

    // layer 3
    spmm_kernel<256, true><<<dim3(NN / 4, Gn), 256, 0, s0>>>(nullptr, 256);
    gemm_tc_kernel<256><<<dim3(10, 2, Gn), 256, 0, s0>>>(2, b3, 512);
    cudaEventRecord(g_pipe.e3, s0);
    cudaStreamWaitEvent(sc, g_pipe.e3, 0);
    conv_pool_kernel<<<dim3(2, 30, Gn), 256, 0, sc>>>(cw, cb, out, 3);

    // layer 4
    spmm_kernel<256, true><<<dim3(NN / 4, Gn), 256, 0, s0>>>(nullptr, 512);
    gemm_tc_kernel<256><<<dim3(10, 2, Gn), 256, 0, s0>>>(3, b4, 768);
    cudaEventRecord(g_pipe.e4, s0);
    cudaStreamWaitEvent(sc, g_pipe.e4, 0);
    conv_pool_kernel<<<dim3(3, 30, Gn), 256, 0, sc>>>(cw, cb, out, 5);

    // join the fork back into the capture stream
    cudaEventRecord(g_pipe.ej, sc);
    cudaStreamWaitEvent(s0, g_pipe.ej, 0);
}

// round 15
// speedup vs baseline: 1.3375x; 1.0299x over previous
#include <cuda_runtime.h>
#include <cuda_bf16.h>
#include <cstdint>
#include <cstddef>

#define Gn   32
#define NN   1200
#define EE   19200
#define SUMH 1024

// ---------------- static scratch (no cudaMalloc allowed) ----------------
__device__ float g_hcat[(size_t)Gn * NN * SUMH];       // concat(h1..h4), conv input
__device__ uint32_t g_Ahi[(size_t)Gn * NN * 128];      // spmm out, hi bf16 k-pairs
__device__ uint32_t g_Alo[(size_t)Gn * NN * 128];      // spmm out, lo bf16 k-pairs
__device__ uint32_t g_Bhi[4 * 256 * 128];              // W splits, [layer][n][kpair]
__device__ uint32_t g_Blo[4 * 256 * 128];
__device__ int   g_rowptr[Gn * (NN + 1)];
__device__ int   g_esrc[Gn * EE];
__device__ float g_esc[Gn * EE];
__device__ float g_sin[Gn * NN];

__device__ __forceinline__ uint32_t pack_bf16x2(__nv_bfloat16 lo, __nv_bfloat16 hi) {
    return (uint32_t)__bfloat16_as_ushort(hi) << 16 | (uint32_t)__bfloat16_as_ushort(lo);
}
__device__ __forceinline__ void split_bf16(float x, __nv_bfloat16& h, __nv_bfloat16& l) {
    h = __float2bfloat16(x);
    l = __float2bfloat16(x - __bfloat162float(h));
}
__device__ __forceinline__ void mma_bf16(float* c, const uint32_t* a, uint32_t b0, uint32_t b1) {
    asm volatile("mma.sync.aligned.m16n8k16.row.col.f32.bf16.bf16.f32 "
        "{%0,%1,%2,%3}, {%4,%5,%6,%7}, {%8,%9}, {%0,%1,%2,%3};"
        : "+f"(c[0]), "+f"(c[1]), "+f"(c[2]), "+f"(c[3])
        : "r"(a[0]), "r"(a[1]), "r"(a[2]), "r"(a[3]), "r"(b0), "r"(b1));
}

// ---------------- CSR build + degree scales (one CTA per graph) ----------------
__global__ void build_csr_kernel(const int* __restrict__ src, const int* __restrict__ dst) {
    __shared__ int s_in[NN];
    __shared__ int s_out[NN];
    __shared__ int s_ptr[NN + 1];
    int g = blockIdx.x, t = threadIdx.x;
    for (int i = t; i < NN; i += blockDim.x) { s_in[i] = 0; s_out[i] = 0; }
    __syncthreads();
    const int* sg = src + g * EE;
    const int* dg = dst + g * EE;
    for (int e = t; e < EE; e += blockDim.x) {
        atomicAdd(&s_out[sg[e]], 1);
        atomicAdd(&s_in[dg[e]], 1);
    }
    __syncthreads();
    for (int i = t; i < NN; i += blockDim.x) {
        int id = s_in[i] < 1 ? 1 : s_in[i];
        g_sin[g * NN + i] = rsqrtf((float)id);
    }
    if (t == 0) {
        int run = 0;
        for (int i = 0; i < NN; i++) { s_ptr[i] = run; run += s_in[i]; }
        s_ptr[NN] = run;
    }
    __syncthreads();
    for (int i = t; i <= NN; i += blockDim.x) g_rowptr[g * (NN + 1) + i] = s_ptr[i];
    for (int i = t; i < NN; i += blockDim.x) s_in[i] = s_ptr[i];   // write cursors
    __syncthreads();
    for (int e = t; e < EE; e += blockDim.x) {
        int d = dg[e];
        int s = sg[e];
        int pos = atomicAdd(&s_in[d], 1);
        int od = s_out[s] < 1 ? 1 : s_out[s];
        g_esrc[g * EE + pos] = s;
        g_esc[g * EE + pos]  = rsqrtf((float)od);
    }
}

// ---------------- W pre-split: g_B{hi,lo}[l][n][kpair] = packed bf16 pair over k ----------------
__global__ void convert_w_kernel(const float* __restrict__ W1, const float* __restrict__ W2,
                                 const float* __restrict__ W3, const float* __restrict__ W4) {
    int l = blockIdx.y;
    const float* W = (l == 0) ? W1 : (l == 1) ? W2 : (l == 2) ? W3 : W4;
    int K = (l == 0) ? 128 : 256;
    int idx = blockIdx.x * 256 + threadIdx.x;
    if (idx >= 256 * (K / 2)) return;
    int n = idx / (K / 2), kp = idx - n * (K / 2);
    float w0 = W[(size_t)(2 * kp) * 256 + n];
    float w1 = W[(size_t)(2 * kp + 1) * 256 + n];
    __nv_bfloat16 h0, l0, h1, l1;
    split_bf16(w0, h0, l0);
    split_bf16(w1, h1, l1);
    size_t o = (size_t)l * 256 * 128 + (size_t)n * (K / 2) + kp;
    g_Bhi[o] = pack_bf16x2(h0, h1);
    g_Blo[o] = pack_bf16x2(l0, l1);
}

// ---------------- SpMM -> bf16 hi/lo planes ----------------
template <int D, bool FROM_HCAT>
__global__ __launch_bounds__(256) void spmm_kernel(const float* __restrict__ hext, int col_off,
                                                   int gbase) {
    constexpr int LPN = D / 4;
    constexpr int NPB = 256 / LPN;
    int g = blockIdx.y + gbase;
    int lane = threadIdx.x & (LPN - 1);
    int ni   = threadIdx.x / LPN;
    int v = blockIdx.x * NPB + ni;

    const int* rp = g_rowptr + g * (NN + 1);
    int beg = rp[v], end = rp[v + 1];
    const int*   es  = g_esrc + g * EE;
    const float* esc = g_esc  + g * EE;

    float4 acc = make_float4(0.f, 0.f, 0.f, 0.f);
    const float* base;
    size_t rstride;
    if (FROM_HCAT) { base = g_hcat + (size_t)g * NN * SUMH + col_off + 4 * lane; rstride = SUMH; }
    else           { base = hext   + (size_t)g * NN * D    + 4 * lane;           rstride = D;    }

    #pragma unroll 4
    for (int e = beg; e < end; e++) {
        int s = es[e];
        float sc = esc[e];
        float4 hv = *(const float4*)(base + (size_t)s * rstride);
        acc.x += hv.x * sc; acc.y += hv.y * sc;
        acc.z += hv.z * sc; acc.w += hv.w * sc;
    }
    float si = g_sin[g * NN + v];
    float va[4] = {acc.x * si, acc.y * si, acc.z * si, acc.w * si};
    __nv_bfloat16 h[4], l[4];
    #pragma unroll
    for (int j = 0; j < 4; j++) split_bf16(va[j], h[j], l[j]);
    size_t o32 = ((size_t)g * NN + v) * (D / 2) + 2 * lane;   // uint32 index
    *(uint2*)&g_Ahi[o32] = make_uint2(pack_bf16x2(h[0], h[1]), pack_bf16x2(h[2], h[3]));
    *(uint2*)&g_Alo[o32] = make_uint2(pack_bf16x2(l[0], l[1]), pack_bf16x2(l[2], l[3]));
}

// ---------------- tensor-core GEMM (mma.sync bf16x2 split, ping-pong smem) ----------------
template <int K>
__global__ __launch_bounds__(256) void gemm_tc_kernel(int layer,
                                                      const float* __restrict__ bias,
                                                      int col_off, int gbase) {
    __shared__ uint32_t Ah[2][8][136], Al[2][8][136], Bh[2][8][136], Bl[2][8][136];
    constexpr int KP = K / 2;          // kpairs per row
    constexpr int NCH = K / 16;        // chunks
    int g = blockIdx.z + gbase;
    int m0 = blockIdx.x * 128, n0 = blockIdx.y * 128;
    int tid = threadIdx.x;
    int lane = tid & 31, wid = tid >> 5;
    int wm = wid & 3, wn = wid >> 2;
    int gid = lane >> 2, tig = lane & 3;

    float acc[2][8][4];
    #pragma unroll
    for (int mi = 0; mi < 2; mi++)
        #pragma unroll
        for (int nj = 0; nj < 8; nj++)
            #pragma unroll
            for (int q = 0; q < 4; q++) acc[mi][nj][q] = 0.f;

    const uint32_t* gAhp = g_Ahi + (size_t)g * NN * KP;
    const uint32_t* gAlp = g_Alo + (size_t)g * NN * KP;
    const uint32_t* gBhp = g_Bhi + (size_t)layer * 256 * 128;
    const uint32_t* gBlp = g_Blo + (size_t)layer * 256 * 128;

    int lrow = tid >> 1;               // 0..127 (m or n within tile)
    int kpb  = (tid & 1) * 4;          // kpair base 0 or 4
    bool a_ok = (m0 + lrow) < NN;

    uint4 rah, ral, rbh, rbl;
    {
        if (a_ok) {
            rah = *(const uint4*)&gAhp[(size_t)(m0 + lrow) * KP + kpb];
            ral = *(const uint4*)&gAlp[(size_t)(m0 + lrow) * KP + kpb];
        } else { rah = make_uint4(0, 0, 0, 0); ral = rah; }
        rbh = *(const uint4*)&gBhp[(size_t)(n0 + lrow) * KP + kpb];
        rbl = *(const uint4*)&gBlp[(size_t)(n0 + lrow) * KP + kpb];
        Ah[0][kpb + 0][lrow] = rah.x; Ah[0][kpb + 1][lrow] = rah.y;
        Ah[0][kpb + 2][lrow] = rah.z; Ah[0][kpb + 3][lrow] = rah.w;
        Al[0][kpb + 0][lrow] = ral.x; Al[0][kpb + 1][lrow] = ral.y;
        Al[0][kpb + 2][lrow] = ral.z; Al[0][kpb + 3][lrow] = ral.w;
        Bh[0][kpb + 0][lrow] = rbh.x; Bh[0][kpb + 1][lrow] = rbh.y;
        Bh[0][kpb + 2][lrow] = rbh.z; Bh[0][kpb + 3][lrow] = rbh.w;
        Bl[0][kpb + 0][lrow] = rbl.x; Bl[0][kpb + 1][lrow] = rbl.y;
        Bl[0][kpb + 2][lrow] = rbl.z; Bl[0][kpb + 3][lrow] = rbl.w;
    }
    __syncthreads();

    for (int ch = 0; ch < NCH; ch++) {
        int cur = ch & 1, nxt = cur ^ 1;
        bool have_next = (ch + 1) < NCH;
        if (have_next) {
            int kq = (ch + 1) * 8 + kpb;
            if (a_ok) {
                rah = *(const uint4*)&gAhp[(size_t)(m0 + lrow) * KP + kq];
                ral = *(const uint4*)&gAlp[(size_t)(m0 + lrow) * KP + kq];
            }
            rbh = *(const uint4*)&gBhp[(size_t)(n0 + lrow) * KP + kq];
            rbl = *(const uint4*)&gBlp[(size_t)(n0 + lrow) * KP + kq];
        }

        uint32_t ah[2][4], al[2][4];
        #pragma unroll
        for (int mi = 0; mi < 2; mi++) {
            int m = wm * 32 + mi * 16 + gid;
            ah[mi][0] = Ah[cur][tig][m];     ah[mi][1] = Ah[cur][tig][m + 8];
            ah[mi][2] = Ah[cur][tig + 4][m]; ah[mi][3] = Ah[cur][tig + 4][m + 8];
            al[mi][0] = Al[cur][tig][m];     al[mi][1] = Al[cur][tig][m + 8];
            al[mi][2] = Al[cur][tig + 4][m]; al[mi][3] = Al[cur][tig + 4][m + 8];
        }
        #pragma unroll
        for (int nj = 0; nj < 8; nj++) {
            int n = wn * 64 + nj * 8 + gid;
            uint32_t bh0 = Bh[cur][tig][n], bh1 = Bh[cur][tig + 4][n];
            uint32_t bl0 = Bl[cur][tig][n], bl1 = Bl[cur][tig + 4][n];
            #pragma unroll
            for (int mi = 0; mi < 2; mi++) {
                mma_bf16(acc[mi][nj], ah[mi], bh0, bh1);   // hi*hi
                mma_bf16(acc[mi][nj], ah[mi], bl0, bl1);   // hi*lo
                mma_bf16(acc[mi][nj], al[mi], bh0, bh1);   // lo*hi
            }
        }

        if (have_next) {
            Ah[nxt][kpb + 0][lrow] = rah.x; Ah[nxt][kpb + 1][lrow] = rah.y;
            Ah[nxt][kpb + 2][lrow] = rah.z; Ah[nxt][kpb + 3][lrow] = rah.w;
            Al[nxt][kpb + 0][lrow] = ral.x; Al[nxt][kpb + 1][lrow] = ral.y;
            Al[nxt][kpb + 2][lrow] = ral.z; Al[nxt][kpb + 3][lrow] = ral.w;
            Bh[nxt][kpb + 0][lrow] = rbh.x; Bh[nxt][kpb + 1][lrow] = rbh.y;
            Bh[nxt][kpb + 2][lrow] = rbh.z; Bh[nxt][kpb + 3][lrow] = rbh.w;
            Bl[nxt][kpb + 0][lrow] = rbl.x; Bl[nxt][kpb + 1][lrow] = rbl.y;
            Bl[nxt][kpb + 2][lrow] = rbl.z; Bl[nxt][kpb + 3][lrow] = rbl.w;
            __syncthreads();
        }
    }

    // epilogue: bias + relu
    #pragma unroll
    for (int nj = 0; nj < 8; nj++) {
        int c = n0 + wn * 64 + nj * 8 + 2 * tig;
        float2 bb = *(const float2*)&bias[c];
        #pragma unroll
        for (int mi = 0; mi < 2; mi++) {
            int r0 = m0 + wm * 32 + mi * 16 + gid;
            int r1 = r0 + 8;
            if (r0 < NN) {
                float vx = acc[mi][nj][0] + bb.x;
                float vy = acc[mi][nj][1] + bb.y;
                float2 v = make_float2(vx > 0.f ? vx : 0.f, vy > 0.f ? vy : 0.f);
                *(float2*)&g_hcat[((size_t)g * NN + r0) * SUMH + col_off + c] = v;
            }
            if (r1 < NN) {
                float vx = acc[mi][nj][2] + bb.x;
                float vy = acc[mi][nj][3] + bb.y;
                float2 v = make_float2(vx > 0.f ? vx : 0.f, vy > 0.f ? vy : 0.f);
                *(float2*)&g_hcat[((size_t)g * NN + r1) * SUMH + col_off + c] = v;
            }
        }
    }
}

// ---------------- fused 13x13 conv (1->3 ch) + max-pool (R11 winner + float2 fill) ----------------
__global__ __launch_bounds__(256) void conv_pool_kernel(const float* __restrict__ cw,
                                                        const float* __restrict__ cb,
                                                        float* __restrict__ out,
                                                        int ct_base, int gbase) {
    __shared__ float  s_img[140][52];
    __shared__ float4 s_w4[169];
    int ct = blockIdx.x + ct_base, p = blockIdx.y, g = blockIdx.z + gbase;
    int tid = threadIdx.x;
    for (int i = tid; i < 169; i += 256)
        s_w4[i] = make_float4(cw[i], cw[169 + i], cw[338 + i], 0.f);

    int base_r = p * 40 - 6, base_c = ct * 128 - 6;
    const float* hg = g_hcat + (size_t)g * NN * SUMH;
    // float2-vectorized fill (base_c even -> 8B-aligned gmem loads)
    for (int idx = tid; idx < 52 * 70; idx += 256) {
        int r = idx / 70, c2 = (idx - r * 70) * 2;
        int gr = base_r + r, gc = base_c + c2;
        float v0 = 0.f, v1 = 0.f;
        if (gr >= 0 && gr < NN) {
            if (gc >= 0 && gc + 1 < SUMH) {
                float2 t = *(const float2*)&hg[(size_t)gr * SUMH + gc];
                v0 = t.x; v1 = t.y;
            } else {
                if (gc >= 0 && gc < SUMH) v0 = hg[(size_t)gr * SUMH + gc];
                if (gc + 1 >= 0 && gc + 1 < SUMH) v1 = hg[(size_t)gr * SUMH + gc + 1];
            }
        }
        s_img[c2][r] = v0;
        s_img[c2 + 1][r] = v1;
    }
    __syncthreads();

    int tx = tid & 127, ty = tid >> 7;
    int wid = tid >> 5;
    int rbase = ty * 20;
    float mx0 = -1e30f, mx1 = -1e30f, mx2 = -1e30f;

    {
        float acc0[20], acc1[20], acc2[20];
        #pragma unroll
        for (int t = 0; t < 20; t++) { acc0[t] = 0.f; acc1[t] = 0.f; acc2[t] = 0.f; }
        #pragma unroll 1
        for (int kci = 0; kci < 13; kci++) {
            int kc = kci + wid;
            if (kc >= 13) kc -= 13;
            float v[32];
            const float4* vcol = (const float4*)&s_img[tx + kc][rbase];
            #pragma unroll
            for (int q = 0; q < 8; q++) {
                float4 t4 = vcol[q];
                v[4 * q + 0] = t4.x; v[4 * q + 1] = t4.y;
                v[4 * q + 2] = t4.z; v[4 * q + 3] = t4.w;
            }
            #pragma unroll
            for (int kr = 0; kr < 13; kr++) {
                float4 w = s_w4[kr * 13 + kc];
                #pragma unroll
                for (int t = 0; t < 20; t++) {
                    float x = v[kr + t];
                    acc0[t] += x * w.x;
                    acc1[t] += x * w.y;
                    acc2[t] += x * w.z;
                }
            }
        }
        #pragma unroll
        for (int t = 0; t < 20; t++) {
            mx0 = fmaxf(mx0, acc0[t]);
            mx1 = fmaxf(mx1, acc1[t]);
            mx2 = fmaxf(mx2, acc2[t]);
        }
    }

    __syncthreads();
    float* red = &s_img[0][0];
    if (ty == 1) { red[tx] = mx0; red[128 + tx] = mx1; red[256 + tx] = mx2; }
    __syncthreads();
    if (ty == 0) {
        mx0 = fmaxf(mx0, red[tx]);
        mx1 = fmaxf(mx1, red[128 + tx]);
        mx2 = fmaxf(mx2, red[256 + tx]);
        int c = ct * 128 + tx;
        out[((size_t)(g * 3 + 0) * 30 + p) * SUMH + c] = mx0 + cb[0];
        out[((size_t)(g * 3 + 1) * 30 + p) * SUMH + c] = mx1 + cb[1];
        out[((size_t)(g * 3 + 2) * 30 + p) * SUMH + c] = mx2 + cb[2];
    }
}

// ---------------- streams + events (static init; no tracked device allocs) ----------------
struct PipeRes {
    cudaStream_t sB = nullptr, scA = nullptr, scB = nullptr;
    cudaEvent_t eF = nullptr;
    cudaEvent_t eA[4] = {}, eB[4] = {};
    cudaEvent_t ejA = nullptr, ejB = nullptr;
    PipeRes() {
        cudaStreamCreateWithFlags(&sB,  cudaStreamNonBlocking);
        cudaStreamCreateWithFlags(&scA, cudaStreamNonBlocking);
        cudaStreamCreateWithFlags(&scB, cudaStreamNonBlocking);
        cudaEventCreateWithFlags(&eF, cudaEventDisableTiming);
        for (int i = 0; i < 4; i++) {
            cudaEventCreateWithFlags(&eA[i], cudaEventDisableTiming);
            cudaEventCreateWithFlags(&eB[i], cudaEventDisableTiming);
        }
        cudaEventCreateWithFlags(&ejA, cudaEventDisableTiming);
        cudaEventCreateWithFlags(&ejB, cudaEventDisableTiming);
    }
};
static PipeRes g_pipe;

// ---------------- driver: two 16-graph chains (A on s0, B on sB) ----------------
extern "C" void kernel_launch(void* const* d_in, const int* in_sizes, int n_in,
                              void* d_out, int out_size) {
    const float* feat = (const float*)d_in[0];
    const int*   src  = (const int*)d_in[1];
    const int*   dst  = (const int*)d_in[2];
    const float* W1 = (const float*)d_in[3];  const float* b1 = (const float*)d_in[4];
    const float* W2 = (const float*)d_in[5];  const float* b2 = (const float*)d_in[6];
    const float* W3 = (const float*)d_in[7];  const float* b3 = (const float*)d_in[8];
    const float* W4 = (const float*)d_in[9];  const float* b4 = (const float*)d_in[10];
    const float* cw = (const float*)d_in[11]; const float* cb = (const float*)d_in[12];
    float* out = (float*)d_out;

    cudaStream_t s0 = (cudaStream_t)0;
    const int HG = Gn / 2;   // 16 graphs per chain

    convert_w_kernel<<<dim3(128, 4), 256, 0, s0>>>(W1, W2, W3, W4);
    build_csr_kernel<<<Gn, 256, 0, s0>>>(src, dst);
    cudaEventRecord(g_pipe.eF, s0);
    cudaStreamWaitEvent(g_pipe.sB, g_pipe.eF, 0);

    const float* biases[4] = {b1, b2, b3, b4};
    const int    coffs[4]  = {0, 256, 512, 768};
    const int    ctb[4]    = {0, 1, 3, 5};
    const int    ctn[4]    = {1, 2, 2, 3};

    // chain A: graphs 0..15 on s0 / conv on scA
    // chain B: graphs 16..31 on sB / conv on scB
    for (int l = 0; l < 4; l++) {
        if (l == 0) {
            spmm_kernel<128, false><<<dim3(NN / 8, HG), 256, 0, s0>>>(feat, 0, 0);
            gemm_tc_kernel<128><<<dim3(10, 2, HG), 256, 0, s0>>>(0, b1, 0, 0);
            spmm_kernel<128, false><<<dim3(NN / 8, HG), 256, 0, g_pipe.sB>>>(feat, 0, HG);
            gemm_tc_kernel<128><<<dim3(10, 2, HG), 256, 0, g_pipe.sB>>>(0, b1, 0, HG);
        } else {
            spmm_kernel<256, true><<<dim3(NN / 4, HG), 256, 0, s0>>>(nullptr, coffs[l - 1], 0);
            gemm_tc_kernel<256><<<dim3(10, 2, HG), 256, 0, s0>>>(l, biases[l], coffs[l], 0);
            spmm_kernel<256, true><<<dim3(NN / 4, HG), 256, 0, g_pipe.sB>>>(nullptr, coffs[l - 1], HG);
            gemm_tc_kernel<256><<<dim3(10, 2, HG), 256, 0, g_pipe.sB>>>(l, biases[l], coffs[l], HG);
        }
        cudaEventRecord(g_pipe.eA[l], s0);
        cudaStreamWaitEvent(g_pipe.scA, g_pipe.eA[l], 0);
        conv_pool_kernel<<<dim3(ctn[l], 30, HG), 256, 0, g_pipe.scA>>>(cw, cb, out, ctb[l], 0);
        cudaEventRecord(g_pipe.eB[l], g_pipe.sB);
        cudaStreamWaitEvent(g_pipe.scB, g_pipe.eB[l], 0);
        conv_pool_kernel<<<dim3(ctn[l], 30, HG), 256, 0, g_pipe.scB>>>(cw, cb, out, ctb[l], HG);
    }

    // join everything back into the capture stream
    cudaEventRecord(g_pipe.ejA, g_pipe.scA);
    cudaStreamWaitEvent(s0, g_pipe.ejA, 0);
    cudaEventRecord(g_pipe.ejB, g_pipe.scB);
    cudaStreamWaitEvent(s0, g_pipe.ejB, 0);
}